// round 1
// baseline (speedup 1.0000x reference)
#include <cuda_runtime.h>
#include <math.h>

#define NQv 4096
#define WAYv 5
#define Cv 64
#define Tv 25
#define EMBv 26
#define BLK 128

// ---------------- scratch (pair-independent precompute) ----------------
__device__ float g_qn[NQv*Cv*Tv];   // channel-mean-subtracted qry
__device__ float g_rq[NQv*Tv];      // 1/sqrt(sum_c qn^2 + 1e-6)
__device__ float g_tp[NQv*Tv];      // projection
__device__ float g_sn[WAYv*Cv*Tv];
__device__ float g_rs[WAYv*Tv];
__device__ float g_sp[WAYv*Tv];

// ---------------- shared-memory layout (floats) ----------------
enum {
  OFF_WQKV = 0,                      // 78 x 26, row stride 27
  OFF_BQKV = OFF_WQKV + 78*27,
  OFF_WATT = OFF_BQKV + 78,          // 26 x 26, stride 27
  OFF_BATT = OFF_WATT + 26*27,
  OFF_WFC1 = OFF_BATT + 26,          // 104 x 26, stride 27
  OFF_BFC1 = OFF_WFC1 + 104*27,
  OFF_WFC2 = OFF_BFC1 + 104,         // 26 x 104, stride 105
  OFF_BFC2 = OFF_WFC2 + 26*105,
  OFF_WDEC = OFF_BFC2 + 26,          // 25 x 26, stride 27
  OFF_BDEC = OFF_WDEC + 25*27,
  OFF_LN1G = OFF_BDEC + 25,
  OFF_LN1B = OFF_LN1G + 26,
  OFF_LN2G = OFF_LN1B + 26,
  OFF_LN2B = OFF_LN2G + 26,
  OFF_POS  = OFF_LN2B + 26,          // 25 x 26
  OFF_SN   = OFF_POS + 650,          // 64 x 25
  OFF_QN   = OFF_SN + 1600,          // 64 x 25
  OFF_RS   = OFF_QN + 1600,
  OFF_RQ   = OFF_RS + 25,
  OFF_SP   = OFF_RQ + 25,
  OFF_TP   = OFF_SP + 25,
  OFF_CORR = OFF_TP + 25,            // 25 x 25 (support i, query j)
  OFF_X    = OFF_CORR + 625,         // 25 x 26, stride 27
  OFF_H    = OFF_X + 25*27,          // 25 x 26, stride 27
  OFF_QKV  = OFF_H + 25*27,          // 25 x 78, stride 79
  OFF_SC   = OFF_QKV + 25*79,        // 2 x 25 x 25 (also reused as As/Aq)
  OFF_AO   = OFF_SC + 1250,          // 25 x 26
  OFF_HID  = OFF_AO + 650,           // 25 x 104, stride 105
  OFF_Y    = OFF_HID + 25*105,       // 25 x 25
  OFF_M25  = OFF_Y + 625,
  OFF_ATTS = OFF_M25 + 32,
  OFF_ATTQ = OFF_ATTS + 32,
  OFF_RED  = OFF_ATTQ + 32,
  SMEM_FLOATS = OFF_RED + 192
};

// ---------------- prep: per-image channel-mean sub + l2 + proj ----------------
__global__ void prep_kernel(const float* __restrict__ in,
                            const float* __restrict__ pw,
                            const float* __restrict__ pb,
                            float* __restrict__ on,
                            float* __restrict__ orr,
                            float* __restrict__ op)
{
  int img = blockIdx.x;
  int t = threadIdx.x;
  if (t >= Tv) return;
  const float* base = in + img*Cv*Tv;
  float v[Cv];
  float s = 0.f;
#pragma unroll
  for (int c = 0; c < Cv; c++){ v[c] = base[c*Tv + t]; s += v[c]; }
  float m = s * (1.f/64.f);
  float ss0=0.f, ss1=0.f, pj0=0.f, pj1=0.f;
#pragma unroll
  for (int c = 0; c < Cv; c += 2){
    float d0 = v[c]-m, d1 = v[c+1]-m;
    on[img*Cv*Tv + c*Tv + t]     = d0;
    on[img*Cv*Tv + (c+1)*Tv + t] = d1;
    ss0 += d0*d0; ss1 += d1*d1;
    pj0 += d0*pw[c]; pj1 += d1*pw[c+1];
  }
  orr[img*Tv + t] = 1.f/sqrtf(ss0+ss1 + 1e-6f);
  op[img*Tv + t]  = pj0+pj1 + pb[0];
}

// ---------------- one pre-LN transformer block, in-place on sm[OFF_X] ----------------
__device__ __forceinline__ void xblock(float* sm, int tid)
{
  // LN1 -> H
  if (tid < 25) {
    float* xr = sm + OFF_X + tid*27;
    float s = 0.f;
#pragma unroll
    for (int e = 0; e < 26; e++) s += xr[e];
    float m = s * (1.f/26.f);
    float v = 0.f;
#pragma unroll
    for (int e = 0; e < 26; e++){ float d = xr[e]-m; v += d*d; }
    float r = 1.f/sqrtf(v*(1.f/26.f) + 1e-6f);
    float* hr = sm + OFF_H + tid*27;
#pragma unroll
    for (int e = 0; e < 26; e++)
      hr[e] = (xr[e]-m)*r*sm[OFF_LN1G+e] + sm[OFF_LN1B+e];
  }
  __syncthreads();

  // QKV: 25 x 78
  for (int idx = tid; idx < 25*78; idx += BLK){
    int t = idx / 78, n = idx % 78;
    const float* hr = sm + OFF_H + t*27;
    const float* wr = sm + OFF_WQKV + n*27;
    float a0 = sm[OFF_BQKV+n], a1 = 0.f;
#pragma unroll
    for (int e = 0; e < 26; e += 2){ a0 += hr[e]*wr[e]; a1 += hr[e+1]*wr[e+1]; }
    sm[OFF_QKV + t*79 + n] = a0 + a1;
  }
  __syncthreads();

  // scores: 2 heads x 25 x 25, scaled
  for (int idx = tid; idx < 1250; idx += BLK){
    int hd = idx / 625, r2 = idx % 625, i = r2/25, j = r2%25;
    const float* qr = sm + OFF_QKV + i*79 + hd*13;
    const float* kr = sm + OFF_QKV + j*79 + 26 + hd*13;
    float a0 = 0.f, a1 = 0.f;
#pragma unroll
    for (int d = 0; d < 12; d += 2){ a0 += qr[d]*kr[d]; a1 += qr[d+1]*kr[d+1]; }
    a0 += qr[12]*kr[12];
    sm[OFF_SC + hd*625 + i*25 + j] = (a0+a1) * 0.2773500981126146f; // 13^-0.5
  }
  __syncthreads();

  // softmax per (head,row)
  if (tid < 50){
    int hd = tid/25, i = tid%25;
    float* row = sm + OFF_SC + hd*625 + i*25;
    float mx = row[0];
#pragma unroll
    for (int j = 1; j < 25; j++) mx = fmaxf(mx, row[j]);
    float s = 0.f;
#pragma unroll
    for (int j = 0; j < 25; j++){ float e = expf(row[j]-mx); row[j] = e; s += e; }
    float is = 1.f/s;
#pragma unroll
    for (int j = 0; j < 25; j++) row[j] *= is;
  }
  __syncthreads();

  // attn out = A @ V  (25 x 26)
  for (int idx = tid; idx < 650; idx += BLK){
    int t = idx/26, f = idx%26, hd = f/13, d = f%13;
    const float* ar = sm + OFF_SC + hd*625 + t*25;
    const float* vb = sm + OFF_QKV + 52 + hd*13 + d;
    float a0 = 0.f, a1 = 0.f;
#pragma unroll
    for (int j = 0; j < 24; j += 2){ a0 += ar[j]*vb[j*79]; a1 += ar[j+1]*vb[(j+1)*79]; }
    a0 += ar[24]*vb[24*79];
    sm[OFF_AO + t*26 + f] = a0 + a1;
  }
  __syncthreads();

  // proj + residual
  for (int idx = tid; idx < 650; idx += BLK){
    int t = idx/26, e = idx%26;
    const float* ar = sm + OFF_AO + t*26;
    const float* wr = sm + OFF_WATT + e*27;
    float a0 = sm[OFF_BATT+e], a1 = 0.f;
#pragma unroll
    for (int f = 0; f < 26; f += 2){ a0 += ar[f]*wr[f]; a1 += ar[f+1]*wr[f+1]; }
    sm[OFF_X + t*27 + e] += a0 + a1;
  }
  __syncthreads();

  // LN2 -> H
  if (tid < 25) {
    float* xr = sm + OFF_X + tid*27;
    float s = 0.f;
#pragma unroll
    for (int e = 0; e < 26; e++) s += xr[e];
    float m = s * (1.f/26.f);
    float v = 0.f;
#pragma unroll
    for (int e = 0; e < 26; e++){ float d = xr[e]-m; v += d*d; }
    float r = 1.f/sqrtf(v*(1.f/26.f) + 1e-6f);
    float* hr = sm + OFF_H + tid*27;
#pragma unroll
    for (int e = 0; e < 26; e++)
      hr[e] = (xr[e]-m)*r*sm[OFF_LN2G+e] + sm[OFF_LN2B+e];
  }
  __syncthreads();

  // FC1 + exact GELU: 25 x 104
  for (int idx = tid; idx < 2600; idx += BLK){
    int t = idx/104, n = idx%104;
    const float* hr = sm + OFF_H + t*27;
    const float* wr = sm + OFF_WFC1 + n*27;
    float a0 = sm[OFF_BFC1+n], a1 = 0.f;
#pragma unroll
    for (int e = 0; e < 26; e += 2){ a0 += hr[e]*wr[e]; a1 += hr[e+1]*wr[e+1]; }
    float x = a0 + a1;
    sm[OFF_HID + t*105 + n] = 0.5f*x*(1.f + erff(x*0.70710678118654752f));
  }
  __syncthreads();

  // FC2 + residual
  for (int idx = tid; idx < 650; idx += BLK){
    int t = idx/26, e = idx%26;
    const float* hr = sm + OFF_HID + t*105;
    const float* wr = sm + OFF_WFC2 + e*105;
    float a0 = sm[OFF_BFC2+e], a1 = 0.f, a2 = 0.f, a3 = 0.f;
#pragma unroll
    for (int f = 0; f < 104; f += 4){
      a0 += hr[f]*wr[f];   a1 += hr[f+1]*wr[f+1];
      a2 += hr[f+2]*wr[f+2]; a3 += hr[f+3]*wr[f+3];
    }
    sm[OFF_X + t*27 + e] += (a0+a1)+(a2+a3);
  }
  __syncthreads();
}

__device__ __forceinline__ void dec_proj(float* sm, int tid)
{
  for (int idx = tid; idx < 625; idx += BLK){
    int t = idx/25, o = idx%25;
    const float* xr = sm + OFF_X + t*27;
    const float* wr = sm + OFF_WDEC + o*27;
    float a0 = sm[OFF_BDEC+o], a1 = 0.f;
#pragma unroll
    for (int e = 0; e < 26; e += 2){ a0 += xr[e]*wr[e]; a1 += xr[e+1]*wr[e+1]; }
    sm[OFF_Y + t*25 + o] = a0 + a1;
  }
  __syncthreads();
}

// ---------------- main fused kernel: one CTA per (query, way) pair ----------------
__global__ __launch_bounds__(BLK) void pair_kernel(
    const float* __restrict__ pos_x, const float* __restrict__ pos_y,
    const float* __restrict__ ln1_g, const float* __restrict__ ln1_b,
    const float* __restrict__ qkv_w, const float* __restrict__ qkv_b,
    const float* __restrict__ attn_w, const float* __restrict__ attn_b,
    const float* __restrict__ ln2_g, const float* __restrict__ ln2_b,
    const float* __restrict__ fc1_w, const float* __restrict__ fc1_b,
    const float* __restrict__ fc2_w, const float* __restrict__ fc2_b,
    const float* __restrict__ dec_w, const float* __restrict__ dec_b,
    float* __restrict__ out)
{
  extern __shared__ float sm[];
  const int b = blockIdx.x;
  const int q = b / WAYv, w = b % WAYv;
  const int tid = threadIdx.x;

  // ---- stage weights (padded strides) ----
  for (int idx = tid; idx < 78*26; idx += BLK)  sm[OFF_WQKV + (idx/26)*27 + idx%26] = qkv_w[idx];
  for (int idx = tid; idx < 26*26; idx += BLK)  sm[OFF_WATT + (idx/26)*27 + idx%26] = attn_w[idx];
  for (int idx = tid; idx < 104*26; idx += BLK) sm[OFF_WFC1 + (idx/26)*27 + idx%26] = fc1_w[idx];
  for (int idx = tid; idx < 26*104; idx += BLK) sm[OFF_WFC2 + (idx/104)*105 + idx%104] = fc2_w[idx];
  for (int idx = tid; idx < 25*26; idx += BLK)  sm[OFF_WDEC + (idx/26)*27 + idx%26] = dec_w[idx];
  if (tid < 78)  sm[OFF_BQKV+tid] = qkv_b[tid];
  if (tid < 104) sm[OFF_BFC1+tid] = fc1_b[tid];
  if (tid < 26){
    sm[OFF_BATT+tid] = attn_b[tid]; sm[OFF_BFC2+tid] = fc2_b[tid];
    sm[OFF_LN1G+tid] = ln1_g[tid];  sm[OFF_LN1B+tid] = ln1_b[tid];
    sm[OFF_LN2G+tid] = ln2_g[tid];  sm[OFF_LN2B+tid] = ln2_b[tid];
  }
  if (tid >= 26 && tid < 51) sm[OFF_BDEC + tid-26] = dec_b[tid-26];
  // positional embedding: token p=(x,y); e<13 from pos_x[y][e], else pos_y[x][e-13]
  for (int idx = tid; idx < 650; idx += BLK){
    int p = idx/26, e = idx%26, px = p/5, py = p%5;
    sm[OFF_POS+idx] = (e < 13) ? pos_x[py*13 + e] : pos_y[px*13 + (e-13)];
  }
  // ---- stage per-pair tiles ----
  for (int idx = tid; idx < 1600; idx += BLK){
    sm[OFF_SN+idx] = g_sn[w*1600 + idx];
    sm[OFF_QN+idx] = g_qn[q*1600 + idx];
  }
  if (tid < 25){
    sm[OFF_RS+tid] = g_rs[w*25+tid]; sm[OFF_RQ+tid] = g_rq[q*25+tid];
    sm[OFF_SP+tid] = g_sp[w*25+tid]; sm[OFF_TP+tid] = g_tp[q*25+tid];
  }
  __syncthreads();

  // ---- corr[i][j] = rs[i]*rq[j]*sum_c sn[c][i]*qn[c][j] ----
  for (int idx = tid; idx < 625; idx += BLK){
    int i = idx/25, j = idx%25;
    const float* sb = sm + OFF_SN + i;
    const float* qb = sm + OFF_QN + j;
    float a0=0.f,a1=0.f,a2=0.f,a3=0.f;
#pragma unroll
    for (int c = 0; c < 64; c += 4){
      a0 += sb[c*25]*qb[c*25];       a1 += sb[(c+1)*25]*qb[(c+1)*25];
      a2 += sb[(c+2)*25]*qb[(c+2)*25]; a3 += sb[(c+3)*25]*qb[(c+3)*25];
    }
    sm[OFF_CORR+idx] = ((a0+a1)+(a2+a3)) * sm[OFF_RS+i] * sm[OFF_RQ+j];
  }
  __syncthreads();

  // ---- x1: token p (query pos) = [corr[:,p], tp[p]] + pos ----
  for (int idx = tid; idx < 650; idx += BLK){
    int p = idx/26, e = idx%26;
    float v = (e < 25) ? sm[OFF_CORR + e*25 + p] : sm[OFF_TP + p];
    sm[OFF_X + p*27 + e] = v + sm[OFF_POS + p*26 + e];
  }
  __syncthreads();

  xblock(sm, tid);
  dec_proj(sm, tid);      // Y[p][o]

  // ---- x2: token i (support pos) = [Y[e][i]+corr[i][e], sp[i]] + pos ----
  for (int idx = tid; idx < 650; idx += BLK){
    int i = idx/26, e = idx%26;
    float v = (e < 25) ? (sm[OFF_Y + e*25 + i] + sm[OFF_CORR + i*25 + e]) : sm[OFF_SP + i];
    sm[OFF_X + i*27 + e] = v + sm[OFF_POS + i*26 + e];
  }
  __syncthreads();

  xblock(sm, tid);
  dec_proj(sm, tid);      // Y[i][j]

  // refined = Y + corr (into CORR)
  for (int idx = tid; idx < 625; idx += BLK) sm[OFF_CORR+idx] += sm[OFF_Y+idx];
  __syncthreads();

  // ---- attn_s: per column j, gnorm(ddof=1)/5 + softmax over i ----
  // ---- attn_q: per row i, same over j ----
  float* R  = sm + OFF_CORR;
  float* As = sm + OFF_SC;         // reuse scores buffer
  float* Aq = sm + OFF_SC + 625;
  if (tid < 25){
    {
      int j = tid;
      float s = 0.f;
#pragma unroll
      for (int i = 0; i < 25; i++) s += R[i*25+j];
      float m = s * (1.f/25.f);
      float v = 0.f;
#pragma unroll
      for (int i = 0; i < 25; i++){ float d = R[i*25+j]-m; v += d*d; }
      float inv = 1.f/(sqrtf(v*(1.f/24.f) + 1e-5f)*5.f);
      float mx = -1e30f;
#pragma unroll
      for (int i = 0; i < 25; i++){ float val = (R[i*25+j]-m)*inv; As[i*25+j] = val; mx = fmaxf(mx, val); }
      float se = 0.f;
#pragma unroll
      for (int i = 0; i < 25; i++){ float e2 = expf(As[i*25+j]-mx); As[i*25+j] = e2; se += e2; }
      float is = 1.f/se;
#pragma unroll
      for (int i = 0; i < 25; i++) As[i*25+j] *= is;
    }
    {
      int i = tid;
      float s = 0.f;
#pragma unroll
      for (int j = 0; j < 25; j++) s += R[i*25+j];
      float m = s * (1.f/25.f);
      float v = 0.f;
#pragma unroll
      for (int j = 0; j < 25; j++){ float d = R[i*25+j]-m; v += d*d; }
      float inv = 1.f/(sqrtf(v*(1.f/24.f) + 1e-5f)*5.f);
      float mx = -1e30f;
#pragma unroll
      for (int j = 0; j < 25; j++){ float val = (R[i*25+j]-m)*inv; Aq[i*25+j] = val; mx = fmaxf(mx, val); }
      float se = 0.f;
#pragma unroll
      for (int j = 0; j < 25; j++){ float e2 = expf(Aq[i*25+j]-mx); Aq[i*25+j] = e2; se += e2; }
      float is = 1.f/se;
#pragma unroll
      for (int j = 0; j < 25; j++) Aq[i*25+j] *= is;
    }
  }
  __syncthreads();
  if (tid < 25){
    float a = 0.f, bq = 0.f;
#pragma unroll
    for (int k = 0; k < 25; k++){ a += As[tid*25+k]; bq += Aq[k*25+tid]; }
    sm[OFF_ATTS+tid] = a;     // attn_s[i] = sum_j As[i][j]
    sm[OFF_ATTQ+tid] = bq;    // attn_q[j] = sum_i Aq[i][j]
  }
  __syncthreads();

  // ---- attention-weighted pooling + cosine sim ----
  if (tid < 64){
    int c = tid;
    const float* sb = sm + OFF_SN + c*25;
    const float* qb = sm + OFF_QN + c*25;
    float a = 0.f, bq = 0.f;
#pragma unroll
    for (int xy = 0; xy < 25; xy++){ a += sm[OFF_ATTS+xy]*sb[xy]; bq += sm[OFF_ATTQ+xy]*qb[xy]; }
    a *= (1.f/25.f); bq *= (1.f/25.f);
    sm[OFF_RED + c]       = a*bq;
    sm[OFF_RED + 64 + c]  = a*a;
    sm[OFF_RED + 128 + c] = bq*bq;
  }
  __syncthreads();
  if (tid == 0){
    float d=0.f, na=0.f, nb=0.f;
#pragma unroll
    for (int c = 0; c < 64; c++){
      d += sm[OFF_RED+c]; na += sm[OFF_RED+64+c]; nb += sm[OFF_RED+128+c];
    }
    float n1 = fmaxf(sqrtf(na), 1e-8f);
    float n2 = fmaxf(sqrtf(nb), 1e-8f);
    out[b] = d / (n1*n2) * 5.0f;   // /TEMP (0.2)
  }
}

// ---------------- launch ----------------
extern "C" void kernel_launch(void* const* d_in, const int* in_sizes, int n_in,
                              void* d_out, int out_size)
{
  const float* spt    = (const float*)d_in[0];
  const float* qry    = (const float*)d_in[1];
  const float* proj_w = (const float*)d_in[2];
  const float* proj_b = (const float*)d_in[3];
  const float* pos_x  = (const float*)d_in[4];
  const float* pos_y  = (const float*)d_in[5];
  const float* ln1_g  = (const float*)d_in[6];
  const float* ln1_b  = (const float*)d_in[7];
  const float* qkv_w  = (const float*)d_in[8];
  const float* qkv_b  = (const float*)d_in[9];
  const float* attn_w = (const float*)d_in[10];
  const float* attn_b = (const float*)d_in[11];
  const float* ln2_g  = (const float*)d_in[12];
  const float* ln2_b  = (const float*)d_in[13];
  const float* fc1_w  = (const float*)d_in[14];
  const float* fc1_b  = (const float*)d_in[15];
  const float* fc2_w  = (const float*)d_in[16];
  const float* fc2_b  = (const float*)d_in[17];
  const float* dec_w  = (const float*)d_in[18];
  const float* dec_b  = (const float*)d_in[19];
  float* out = (float*)d_out;

  float *qn, *rq, *tp, *sn, *rs, *sp;
  cudaGetSymbolAddress((void**)&qn, g_qn);
  cudaGetSymbolAddress((void**)&rq, g_rq);
  cudaGetSymbolAddress((void**)&tp, g_tp);
  cudaGetSymbolAddress((void**)&sn, g_sn);
  cudaGetSymbolAddress((void**)&rs, g_rs);
  cudaGetSymbolAddress((void**)&sp, g_sp);

  prep_kernel<<<WAYv, 32>>>(spt, proj_w, proj_b, sn, rs, sp);
  prep_kernel<<<NQv, 32>>>(qry, proj_w, proj_b, qn, rq, tp);

  size_t shmem = SMEM_FLOATS * sizeof(float);
  cudaFuncSetAttribute(pair_kernel, cudaFuncAttributeMaxDynamicSharedMemorySize, (int)shmem);
  pair_kernel<<<NQv*WAYv, BLK, shmem>>>(
      pos_x, pos_y, ln1_g, ln1_b, qkv_w, qkv_b, attn_w, attn_b,
      ln2_g, ln2_b, fc1_w, fc1_b, fc2_w, fc2_b, dec_w, dec_b, out);
}

// round 2
// speedup vs baseline: 1.6311x; 1.6311x over previous
#include <cuda_runtime.h>
#include <math.h>

#define NQv 4096
#define WAYv 5
#define Cv 64
#define Tv 25
#define BLK 160   // 5 warps: one per way

// ---------------- global scratch (pair-independent precompute) ----------------
__device__ float g_qn[NQv*Cv*Tv];   // channel-mean-subtracted qry
__device__ float g_rq[NQv*Tv];      // 1/sqrt(sum_c qn^2 + 1e-6)
__device__ float g_tp[NQv*Tv];      // projection
__device__ float g_sn[WAYv*Cv*Tv];
__device__ float g_rs[WAYv*Tv];
__device__ float g_sp[WAYv*Tv];

// ---------------- shared layout (floats). float4-read regions first (16B aligned) ----
enum {
  OFF_WQKV = 0,                      // 78 x 28
  OFF_WATT = OFF_WQKV + 78*28,       // 26 x 28
  OFF_WFC1 = OFF_WATT + 26*28,       // 104 x 28
  OFF_WFC2T= OFF_WFC1 + 104*28,      // 104 x 28  (fc2 transposed: [f][e])
  OFF_WDEC = OFF_WFC2T + 104*28,     // 25 x 28
  OFF_SN   = OFF_WDEC + 25*28,       // 5 x 64 x 28
  OFF_SCR  = OFF_SN + 5*64*28,       // 5 x 25 x 28 per-warp scratch (k/v/Y1/probs)
  OFF_QN   = OFF_SCR + 5*25*28,      // 64 x 28
  OFF_CORR = OFF_QN + 64*28,         // 5 x 25 x 29 (stride 29: lane-transposed reads)
  OFF_BQKV = OFF_CORR + 5*25*29,
  OFF_BATT = OFF_BQKV + 78,
  OFF_BFC1 = OFF_BATT + 26,
  OFF_BFC2 = OFF_BFC1 + 104,
  OFF_BDEC = OFF_BFC2 + 26,
  OFF_LN1G = OFF_BDEC + 25,
  OFF_LN1B = OFF_LN1G + 26,
  OFF_LN2G = OFF_LN1B + 26,
  OFF_LN2B = OFF_LN2G + 26,
  OFF_POS  = OFF_LN2B + 26,          // 25 x 27 (stride 27: lane-strided conflict-free)
  OFF_RS   = OFF_POS + 25*27,        // 5 x 25
  OFF_SP   = OFF_RS + 125,           // 5 x 25
  OFF_RQ   = OFF_SP + 125,           // 25
  OFF_TP   = OFF_RQ + 25,            // 25
  OFF_ATTS = OFF_TP + 25,            // 5 x 32
  OFF_ATTQ = OFF_ATTS + 160,         // 5 x 32
  SMEM_FLOATS = OFF_ATTQ + 160
};

// ---------------- prep: per-image channel-mean sub + l2 + proj ----------------
__global__ void prep_kernel(const float* __restrict__ in,
                            const float* __restrict__ pw,
                            const float* __restrict__ pb,
                            float* __restrict__ on,
                            float* __restrict__ orr,
                            float* __restrict__ op)
{
  int img = blockIdx.x;
  int t = threadIdx.x;
  if (t >= Tv) return;
  const float* base = in + img*Cv*Tv;
  float v[Cv];
  float s = 0.f;
#pragma unroll
  for (int c = 0; c < Cv; c++){ v[c] = base[c*Tv + t]; s += v[c]; }
  float m = s * (1.f/64.f);
  float ss0=0.f, ss1=0.f, pj0=0.f, pj1=0.f;
#pragma unroll
  for (int c = 0; c < Cv; c += 2){
    float d0 = v[c]-m, d1 = v[c+1]-m;
    on[img*Cv*Tv + c*Tv + t]     = d0;
    on[img*Cv*Tv + (c+1)*Tv + t] = d1;
    ss0 += d0*d0; ss1 += d1*d1;
    pj0 += d0*pw[c]; pj1 += d1*pw[c+1];
  }
  orr[img*Tv + t] = rsqrtf(ss0+ss1 + 1e-6f);
  op[img*Tv + t]  = pj0+pj1 + pb[0];
}

// ---------------- register-dot helpers (broadcast float4 weight rows) ----------------
__device__ __forceinline__ float dot26(const float* __restrict__ row, const float (&h)[26]){
  const float4* r4 = (const float4*)row;
  float a0=0.f,a1=0.f,a2=0.f,a3=0.f;
#pragma unroll
  for (int g = 0; g < 6; g++){
    float4 w = r4[g];
    a0 += h[4*g+0]*w.x; a1 += h[4*g+1]*w.y;
    a2 += h[4*g+2]*w.z; a3 += h[4*g+3]*w.w;
  }
  a0 += h[24]*row[24]; a1 += h[25]*row[25];
  return (a0+a1)+(a2+a3);
}

__device__ __forceinline__ float dot13(const float* __restrict__ row, const float (&q)[13]){
  const float4* r4 = (const float4*)row;
  float4 a = r4[0], b = r4[1], c = r4[2];
  float s0 = q[0]*a.x + q[4]*b.x + q[8]*c.x + q[12]*row[12];
  float s1 = q[1]*a.y + q[5]*b.y + q[9]*c.y;
  float s2 = q[2]*a.z + q[6]*b.z + q[10]*c.z;
  float s3 = q[3]*a.w + q[7]*b.w + q[11]*c.w;
  return (s0+s1)+(s2+s3);
}

#define M25 0x01FFFFFFu

// ---------------- pre-LN transformer block, activations in registers ----------------
__device__ __forceinline__ void xblock(float (&x)[26], int lane, float* __restrict__ sm,
                                       float* __restrict__ SCR)
{
  // LN1
  float hh[26];
  {
    float s = 0.f;
#pragma unroll
    for (int e = 0; e < 26; e++) s += x[e];
    float m = s * (1.f/26.f);
    float vv = 0.f;
#pragma unroll
    for (int e = 0; e < 26; e++){ float d = x[e]-m; vv += d*d; }
    float r = rsqrtf(vv*(1.f/26.f) + 1e-6f);
#pragma unroll
    for (int e = 0; e < 26; e++)
      hh[e] = (x[e]-m)*r*sm[OFF_LN1G+e] + sm[OFF_LN1B+e];
  }

  float ao[26];
#pragma unroll
  for (int head = 0; head < 2; head++){
    // q in registers
    float qd[13];
#pragma unroll
    for (int d = 0; d < 13; d++)
      qd[d] = sm[OFF_BQKV + head*13 + d]
            + dot26(sm + OFF_WQKV + (head*13+d)*28, hh);
    // k -> scratch
#pragma unroll 2
    for (int d = 0; d < 13; d++)
      SCR[lane*28 + d] = sm[OFF_BQKV + 26 + head*13 + d]
                       + dot26(sm + OFF_WQKV + (26+head*13+d)*28, hh);
    __syncwarp(M25);

    // scores + softmax (row in registers)
    float p[25];
    float mx = -1e30f;
#pragma unroll
    for (int j = 0; j < 25; j++){
      float s = dot13(SCR + j*28, qd) * 0.2773500981126146f;  // 13^-0.5
      p[j] = s; mx = fmaxf(mx, s);
    }
    float se = 0.f;
#pragma unroll
    for (int j = 0; j < 25; j++){ float e2 = expf(p[j]-mx); p[j] = e2; se += e2; }
    float inv = 1.f/se;
#pragma unroll
    for (int j = 0; j < 25; j++) p[j] *= inv;
    __syncwarp(M25);

    // v -> scratch
#pragma unroll 2
    for (int d = 0; d < 13; d++)
      SCR[lane*28 + d] = sm[OFF_BQKV + 52 + head*13 + d]
                       + dot26(sm + OFF_WQKV + (52+head*13+d)*28, hh);
    __syncwarp(M25);

    // AV
    float od[13];
#pragma unroll
    for (int d = 0; d < 13; d++) od[d] = 0.f;
#pragma unroll
    for (int j = 0; j < 25; j++){
      const float* vr = SCR + j*28;
      const float4* v4 = (const float4*)vr;
      float4 a = v4[0], b = v4[1], c = v4[2];
      float pj = p[j];
      od[0] += pj*a.x; od[1] += pj*a.y; od[2]  += pj*a.z; od[3]  += pj*a.w;
      od[4] += pj*b.x; od[5] += pj*b.y; od[6]  += pj*b.z; od[7]  += pj*b.w;
      od[8] += pj*c.x; od[9] += pj*c.y; od[10] += pj*c.z; od[11] += pj*c.w;
      od[12] += pj*vr[12];
    }
#pragma unroll
    for (int d = 0; d < 13; d++) ao[head*13+d] = od[d];
    __syncwarp(M25);   // AV reads done before next head (or caller) rewrites SCR
  }

  // attn proj + residual
#pragma unroll
  for (int e = 0; e < 26; e++)
    x[e] += sm[OFF_BATT+e] + dot26(sm + OFF_WATT + e*28, ao);

  // LN2
  {
    float s = 0.f;
#pragma unroll
    for (int e = 0; e < 26; e++) s += x[e];
    float m = s * (1.f/26.f);
    float vv = 0.f;
#pragma unroll
    for (int e = 0; e < 26; e++){ float d = x[e]-m; vv += d*d; }
    float r = rsqrtf(vv*(1.f/26.f) + 1e-6f);
#pragma unroll
    for (int e = 0; e < 26; e++)
      hh[e] = (x[e]-m)*r*sm[OFF_LN2G+e] + sm[OFF_LN2B+e];
  }

  // fused FFN: fc2 bias first, then per-n FC1 + exact GELU + scatter via fc2^T row
#pragma unroll
  for (int e = 0; e < 26; e++) x[e] += sm[OFF_BFC2+e];
#pragma unroll 2
  for (int n = 0; n < 104; n++){
    float g = sm[OFF_BFC1+n] + dot26(sm + OFF_WFC1 + n*28, hh);
    g = 0.5f*g*(1.f + erff(g*0.70710678118654752f));
    const float* w2 = sm + OFF_WFC2T + n*28;
    const float4* w4 = (const float4*)w2;
#pragma unroll
    for (int gi = 0; gi < 6; gi++){
      float4 w = w4[gi];
      x[4*gi+0] += g*w.x; x[4*gi+1] += g*w.y;
      x[4*gi+2] += g*w.z; x[4*gi+3] += g*w.w;
    }
    x[24] += g*w2[24]; x[25] += g*w2[25];
  }
}

// ---------------- main fused kernel: CTA = one query x 5 ways, warp per pair ----------
__global__ __launch_bounds__(BLK, 2) void pair_kernel(
    const float* __restrict__ pos_x, const float* __restrict__ pos_y,
    const float* __restrict__ ln1_g, const float* __restrict__ ln1_b,
    const float* __restrict__ qkv_w, const float* __restrict__ qkv_b,
    const float* __restrict__ attn_w, const float* __restrict__ attn_b,
    const float* __restrict__ ln2_g, const float* __restrict__ ln2_b,
    const float* __restrict__ fc1_w, const float* __restrict__ fc1_b,
    const float* __restrict__ fc2_w, const float* __restrict__ fc2_b,
    const float* __restrict__ dec_w, const float* __restrict__ dec_b,
    float* __restrict__ out)
{
  extern __shared__ float sm[];
  const int q = blockIdx.x;
  const int tid = threadIdx.x;

  // ---- stage weights / tiles ----
  for (int idx = tid; idx < 78*26; idx += BLK)  sm[OFF_WQKV + (idx/26)*28 + idx%26] = qkv_w[idx];
  for (int idx = tid; idx < 26*26; idx += BLK)  sm[OFF_WATT + (idx/26)*28 + idx%26] = attn_w[idx];
  for (int idx = tid; idx < 104*26; idx += BLK) sm[OFF_WFC1 + (idx/26)*28 + idx%26] = fc1_w[idx];
  for (int idx = tid; idx < 26*104; idx += BLK){ int e = idx/104, f = idx%104;
                                                 sm[OFF_WFC2T + f*28 + e] = fc2_w[idx]; }
  for (int idx = tid; idx < 25*26; idx += BLK)  sm[OFF_WDEC + (idx/26)*28 + idx%26] = dec_w[idx];
  if (tid < 78)  sm[OFF_BQKV+tid] = qkv_b[tid];
  if (tid < 104) sm[OFF_BFC1+tid] = fc1_b[tid];
  if (tid < 26){
    sm[OFF_BATT+tid] = attn_b[tid]; sm[OFF_BFC2+tid] = fc2_b[tid];
    sm[OFF_LN1G+tid] = ln1_g[tid];  sm[OFF_LN1B+tid] = ln1_b[tid];
    sm[OFF_LN2G+tid] = ln2_g[tid];  sm[OFF_LN2B+tid] = ln2_b[tid];
  }
  if (tid >= 32 && tid < 57) sm[OFF_BDEC + tid-32] = dec_b[tid-32];
  for (int idx = tid; idx < 650; idx += BLK){
    int p = idx/26, e = idx%26, px = p/5, py = p%5;
    sm[OFF_POS + p*27 + e] = (e < 13) ? pos_x[py*13 + e] : pos_y[px*13 + (e-13)];
  }
  for (int idx = tid; idx < 5*1600; idx += BLK){
    int w = idx/1600, r = idx%1600, c = r/25, i = r%25;
    sm[OFF_SN + w*1792 + c*28 + i] = g_sn[idx];
  }
  for (int idx = tid; idx < 1600; idx += BLK){
    int c = idx/25, j = idx%25;
    sm[OFF_QN + c*28 + j] = g_qn[q*1600 + idx];
  }
  for (int idx = tid; idx < 125; idx += BLK){ sm[OFF_RS+idx] = g_rs[idx]; sm[OFF_SP+idx] = g_sp[idx]; }
  if (tid >= 64 && tid < 89){ sm[OFF_RQ + tid-64] = g_rq[q*25 + tid-64];
                              sm[OFF_TP + tid-64] = g_tp[q*25 + tid-64]; }
  __syncthreads();

  const int w    = tid >> 5;      // way
  const int lane = tid & 31;      // token
  float* SNw   = sm + OFF_SN   + w*1792;
  float* SCR   = sm + OFF_SCR  + w*700;
  float* CORR  = sm + OFF_CORR + w*725;
  float* ATTSw = sm + OFF_ATTS + w*32;
  float* ATTQw = sm + OFF_ATTQ + w*32;

  if (lane < 25){
    // ---- corr[i][lane] = rs[i]*rq[lane]* sum_c sn[c][i]*qn[c][lane] ----
    float acc[25];
#pragma unroll
    for (int i = 0; i < 25; i++) acc[i] = 0.f;
    for (int c = 0; c < 64; c++){
      float qc = sm[OFF_QN + c*28 + lane];
      const float* srow = SNw + c*28;
      const float4* s4 = (const float4*)srow;
#pragma unroll
      for (int g = 0; g < 6; g++){
        float4 sv = s4[g];
        acc[4*g+0] += sv.x*qc; acc[4*g+1] += sv.y*qc;
        acc[4*g+2] += sv.z*qc; acc[4*g+3] += sv.w*qc;
      }
      acc[24] += srow[24]*qc;
    }
    float rq = sm[OFF_RQ + lane];
#pragma unroll
    for (int i = 0; i < 25; i++)
      CORR[i*29 + lane] = acc[i] * sm[OFF_RS + w*25 + i] * rq;
    __syncwarp(M25);

    // ---- x1: token p=lane: [corr[:,p], tp[p]] + pos ----
    float x[26];
#pragma unroll
    for (int e = 0; e < 25; e++) x[e] = CORR[e*29 + lane];
    x[25] = sm[OFF_TP + lane];
#pragma unroll
    for (int e = 0; e < 26; e++) x[e] += sm[OFF_POS + lane*27 + e];

    xblock(x, lane, sm, SCR);

    // dec1 -> SCR (Y1[t][o] at SCR[t*28+o])
#pragma unroll 2
    for (int o = 0; o < 25; o++)
      SCR[lane*28 + o] = sm[OFF_BDEC+o] + dot26(sm + OFF_WDEC + o*28, x);
    __syncwarp(M25);

    // ---- x2: token i=lane: [Y1[e][i]+corr[i][e], sp[i]] + pos ----
#pragma unroll
    for (int e = 0; e < 25; e++) x[e] = SCR[e*28 + lane] + CORR[lane*29 + e];
    x[25] = sm[OFF_SP + w*25 + lane];
#pragma unroll
    for (int e = 0; e < 26; e++) x[e] += sm[OFF_POS + lane*27 + e];
    __syncwarp(M25);   // Y1 reads done before block2 reuses SCR

    xblock(x, lane, sm, SCR);

    // dec2 + refined row in registers, write back to CORR
    float y[25];
#pragma unroll
    for (int o = 0; o < 25; o++)
      y[o] = sm[OFF_BDEC+o] + dot26(sm + OFF_WDEC + o*28, x) + CORR[lane*29 + o];
#pragma unroll
    for (int o = 0; o < 25; o++) CORR[lane*29 + o] = y[o];
    __syncwarp(M25);

    // ---- attn_q: row-wise gnorm(ddof=1)/5 + softmax over j (registers) ----
    {
      float s = 0.f;
#pragma unroll
      for (int j = 0; j < 25; j++) s += y[j];
      float m = s*(1.f/25.f);
      float vv = 0.f;
#pragma unroll
      for (int j = 0; j < 25; j++){ float d = y[j]-m; vv += d*d; }
      float inv = 0.2f * rsqrtf(vv*(1.f/24.f) + 1e-5f);
      float mx = -1e30f;
#pragma unroll
      for (int j = 0; j < 25; j++){ float z = (y[j]-m)*inv; y[j] = z; mx = fmaxf(mx, z); }
      float se = 0.f;
#pragma unroll
      for (int j = 0; j < 25; j++){ float e2 = expf(y[j]-mx); y[j] = e2; se += e2; }
      float is = 1.f/se;
#pragma unroll
      for (int j = 0; j < 25; j++) SCR[lane*28 + j] = y[j]*is;
    }
    __syncwarp(M25);
    {
      float s = 0.f;
#pragma unroll
      for (int i = 0; i < 25; i++) s += SCR[i*28 + lane];
      ATTQw[lane] = s;                 // attn_q[j=lane]
    }
    __syncwarp(M25);

    // ---- attn_s: column-wise gnorm + softmax over i (lane = column j) ----
    {
      float col[25];
#pragma unroll
      for (int i = 0; i < 25; i++) col[i] = CORR[i*29 + lane];
      float s = 0.f;
#pragma unroll
      for (int i = 0; i < 25; i++) s += col[i];
      float m = s*(1.f/25.f);
      float vv = 0.f;
#pragma unroll
      for (int i = 0; i < 25; i++){ float d = col[i]-m; vv += d*d; }
      float inv = 0.2f * rsqrtf(vv*(1.f/24.f) + 1e-5f);
      float mx = -1e30f;
#pragma unroll
      for (int i = 0; i < 25; i++){ float z = (col[i]-m)*inv; col[i] = z; mx = fmaxf(mx, z); }
      float se = 0.f;
#pragma unroll
      for (int i = 0; i < 25; i++){ float e2 = expf(col[i]-mx); col[i] = e2; se += e2; }
      float is = 1.f/se;
#pragma unroll
      for (int i = 0; i < 25; i++) SCR[i*28 + lane] = col[i]*is;
    }
    __syncwarp(M25);
    {
      float s = 0.f;
#pragma unroll
      for (int j = 0; j < 25; j++) s += SCR[lane*28 + j];
      ATTSw[lane] = s;                 // attn_s[i=lane]
    }
  }
  __syncwarp();   // full warp: fences ATTS/ATTQ for lanes 25-31

  // ---- pooling (lane = channel, 2 channels per lane) + cosine sim ----
  {
    int c0 = lane, c1 = lane + 32;
    float sp0=0.f, sp1=0.f, qp0=0.f, qp1=0.f;
#pragma unroll
    for (int t = 0; t < 25; t++){
      float as_ = ATTSw[t], aq_ = ATTQw[t];
      sp0 += as_ * SNw[c0*28 + t];
      sp1 += as_ * SNw[c1*28 + t];
      qp0 += aq_ * sm[OFF_QN + c0*28 + t];
      qp1 += aq_ * sm[OFF_QN + c1*28 + t];
    }
    sp0 *= 0.04f; sp1 *= 0.04f; qp0 *= 0.04f; qp1 *= 0.04f;
    float dd = sp0*qp0 + sp1*qp1;
    float na = sp0*sp0 + sp1*sp1;
    float nb = qp0*qp0 + qp1*qp1;
#pragma unroll
    for (int off = 16; off; off >>= 1){
      dd += __shfl_xor_sync(0xFFFFFFFFu, dd, off);
      na += __shfl_xor_sync(0xFFFFFFFFu, na, off);
      nb += __shfl_xor_sync(0xFFFFFFFFu, nb, off);
    }
    if (lane == 0){
      float n1 = fmaxf(sqrtf(na), 1e-8f);
      float n2 = fmaxf(sqrtf(nb), 1e-8f);
      out[q*WAYv + w] = dd / (n1*n2) * 5.0f;   // /TEMP
    }
  }
}

// ---------------- launch ----------------
extern "C" void kernel_launch(void* const* d_in, const int* in_sizes, int n_in,
                              void* d_out, int out_size)
{
  const float* spt    = (const float*)d_in[0];
  const float* qry    = (const float*)d_in[1];
  const float* proj_w = (const float*)d_in[2];
  const float* proj_b = (const float*)d_in[3];
  const float* pos_x  = (const float*)d_in[4];
  const float* pos_y  = (const float*)d_in[5];
  const float* ln1_g  = (const float*)d_in[6];
  const float* ln1_b  = (const float*)d_in[7];
  const float* qkv_w  = (const float*)d_in[8];
  const float* qkv_b  = (const float*)d_in[9];
  const float* attn_w = (const float*)d_in[10];
  const float* attn_b = (const float*)d_in[11];
  const float* ln2_g  = (const float*)d_in[12];
  const float* ln2_b  = (const float*)d_in[13];
  const float* fc1_w  = (const float*)d_in[14];
  const float* fc1_b  = (const float*)d_in[15];
  const float* fc2_w  = (const float*)d_in[16];
  const float* fc2_b  = (const float*)d_in[17];
  const float* dec_w  = (const float*)d_in[18];
  const float* dec_b  = (const float*)d_in[19];
  float* out = (float*)d_out;

  float *qn, *rq, *tp, *sn, *rs, *sp;
  cudaGetSymbolAddress((void**)&qn, g_qn);
  cudaGetSymbolAddress((void**)&rq, g_rq);
  cudaGetSymbolAddress((void**)&tp, g_tp);
  cudaGetSymbolAddress((void**)&sn, g_sn);
  cudaGetSymbolAddress((void**)&rs, g_rs);
  cudaGetSymbolAddress((void**)&sp, g_sp);

  prep_kernel<<<WAYv, 32>>>(spt, proj_w, proj_b, sn, rs, sp);
  prep_kernel<<<NQv, 32>>>(qry, proj_w, proj_b, qn, rq, tp);

  size_t shmem = SMEM_FLOATS * sizeof(float);
  static int configured = -1;
  if (configured < 0){
    cudaFuncSetAttribute(pair_kernel, cudaFuncAttributeMaxDynamicSharedMemorySize, (int)shmem);
    configured = 1;
  }
  pair_kernel<<<NQv, BLK, shmem>>>(
      pos_x, pos_y, ln1_g, ln1_b, qkv_w, qkv_b, attn_w, attn_b,
      ln2_g, ln2_b, fc1_w, fc1_b, fc2_w, fc2_b, dec_w, dec_b, out);
}

// round 4
// speedup vs baseline: 1.7845x; 1.0940x over previous
#include <cuda_runtime.h>
#include <math.h>

#define NQv 4096
#define WAYv 5
#define Cv 64
#define Tv 25
#define BLK 160   // 5 warps: one per way

typedef unsigned long long u64;

// ---------------- f32x2 packed helpers ----------------
__device__ __forceinline__ u64 pack2(float lo, float hi){
  u64 r; asm("mov.b64 %0, {%1, %2};" : "=l"(r) : "f"(lo), "f"(hi)); return r;
}
__device__ __forceinline__ void unpack2(u64 v, float& lo, float& hi){
  asm("mov.b64 {%0, %1}, %2;" : "=f"(lo), "=f"(hi) : "l"(v));
}
__device__ __forceinline__ u64 fma2(u64 a, u64 b, u64 c){
  u64 d; asm("fma.rn.f32x2 %0, %1, %2, %3;" : "=l"(d) : "l"(a), "l"(b), "l"(c)); return d;
}
__device__ __forceinline__ u64 add2(u64 a, u64 b){
  u64 d; asm("add.rn.f32x2 %0, %1, %2;" : "=l"(d) : "l"(a), "l"(b)); return d;
}

// ---------------- global scratch (pair-independent precompute) ----------------
__device__ float g_qn[NQv*Cv*Tv];
__device__ float g_rq[NQv*Tv];
__device__ float g_tp[NQv*Tv];
__device__ float g_sn[WAYv*Cv*Tv];
__device__ float g_rs[WAYv*Tv];
__device__ float g_sp[WAYv*Tv];

// ---------------- shared layout (floats), 16B-aligned vector regions first ----------
enum {
  OFF_WQKV = 0,                      // 78 x 28
  OFF_WATT = OFF_WQKV + 78*28,       // 26 x 28
  OFF_WFC1 = OFF_WATT + 26*28,       // 104 x 28
  OFF_WFC2T= OFF_WFC1 + 104*28,      // 104 x 28 (fc2 transposed)
  OFF_WDEC = OFF_WFC2T + 104*28,     // 25 x 28
  OFF_SN   = OFF_WDEC + 25*28,       // 5 x 64 x 28
  OFF_SCR  = OFF_SN + 5*64*28,       // 5 x 25 x 28
  OFF_QN   = OFF_SCR + 5*25*28,      // 64 x 28
  OFF_CORR = OFF_QN + 64*28,         // 5 x 25 x 29
  OFF_BQKV = OFF_CORR + 5*25*29,
  OFF_BATT = OFF_BQKV + 78,
  OFF_BFC1 = OFF_BATT + 26,
  OFF_BFC2 = OFF_BFC1 + 104,
  OFF_BDEC = OFF_BFC2 + 26,
  OFF_LN1G = OFF_BDEC + 25,
  OFF_LN1B = OFF_LN1G + 26,
  OFF_LN2G = OFF_LN1B + 26,
  OFF_LN2B = OFF_LN2G + 26,
  OFF_POS  = OFF_LN2B + 26,          // 25 x 27
  OFF_RS   = OFF_POS + 25*27,
  OFF_SP   = OFF_RS + 125,
  OFF_RQ   = OFF_SP + 125,
  OFF_TP   = OFF_RQ + 25,
  OFF_ATTS = OFF_TP + 25,
  OFF_ATTQ = OFF_ATTS + 160,
  SMEM_FLOATS = OFF_ATTQ + 160
};

// ---------------- prep ----------------
__global__ void prep_kernel(const float* __restrict__ in,
                            const float* __restrict__ pw,
                            const float* __restrict__ pb,
                            float* __restrict__ on,
                            float* __restrict__ orr,
                            float* __restrict__ op)
{
  int img = blockIdx.x;
  int t = threadIdx.x;
  if (t >= Tv) return;
  const float* base = in + img*Cv*Tv;
  float v[Cv];
  float s = 0.f;
#pragma unroll
  for (int c = 0; c < Cv; c++){ v[c] = base[c*Tv + t]; s += v[c]; }
  float m = s * (1.f/64.f);
  float ss0=0.f, ss1=0.f, pj0=0.f, pj1=0.f;
#pragma unroll
  for (int c = 0; c < Cv; c += 2){
    float d0 = v[c]-m, d1 = v[c+1]-m;
    on[img*Cv*Tv + c*Tv + t]     = d0;
    on[img*Cv*Tv + (c+1)*Tv + t] = d1;
    ss0 += d0*d0; ss1 += d1*d1;
    pj0 += d0*pw[c]; pj1 += d1*pw[c+1];
  }
  orr[img*Tv + t] = rsqrtf(ss0+ss1 + 1e-6f);
  op[img*Tv + t]  = pj0+pj1 + pb[0];
}

// ---------------- packed dot helpers ----------------
// 26-dot: h packed into 13 f32x2 regs; row = smem, 16B aligned, stride 28 floats.
__device__ __forceinline__ float dot26p(const float* __restrict__ row, const u64 (&h2)[13]){
  const ulonglong2* r2 = (const ulonglong2*)row;
  u64 a0 = 0ull, a1 = 0ull;
  ulonglong2 v0 = r2[0], v1 = r2[1], v2 = r2[2];
  a0 = fma2(v0.x, h2[0], a0);  a1 = fma2(v0.y, h2[1], a1);
  a0 = fma2(v1.x, h2[2], a0);  a1 = fma2(v1.y, h2[3], a1);
  a0 = fma2(v2.x, h2[4], a0);  a1 = fma2(v2.y, h2[5], a1);
  ulonglong2 v3 = r2[3], v4 = r2[4], v5 = r2[5];
  a0 = fma2(v3.x, h2[6], a0);  a1 = fma2(v3.y, h2[7], a1);
  a0 = fma2(v4.x, h2[8], a0);  a1 = fma2(v4.y, h2[9], a1);
  a0 = fma2(v5.x, h2[10], a0); a1 = fma2(v5.y, h2[11], a1);
  a0 = fma2(((const u64*)row)[12], h2[12], a0);
  float l0,hh0,l1,hh1;
  unpack2(a0,l0,hh0); unpack2(a1,l1,hh1);
  return (l0+hh0)+(l1+hh1);
}

// 13-dot (attention scores): q packed 6 pairs + scalar q12.
__device__ __forceinline__ float dot13p(const float* __restrict__ row,
                                        const u64 (&qp)[6], float q12){
  const ulonglong2* r2 = (const ulonglong2*)row;
  ulonglong2 v0 = r2[0], v1 = r2[1], v2 = r2[2];
  u64 a0 = 0ull, a1 = 0ull;
  a0 = fma2(v0.x, qp[0], a0); a1 = fma2(v0.y, qp[1], a1);
  a0 = fma2(v1.x, qp[2], a0); a1 = fma2(v1.y, qp[3], a1);
  a0 = fma2(v2.x, qp[4], a0); a1 = fma2(v2.y, qp[5], a1);
  float l0,hh0,l1,hh1;
  unpack2(a0,l0,hh0); unpack2(a1,l1,hh1);
  return (l0+hh0)+(l1+hh1) + q12*row[12];
}

#define M25 0x01FFFFFFu

// ---------------- pre-LN transformer block, packed activations ----------------
__device__ __forceinline__ void xblock(float (&x)[26], int lane, float* __restrict__ sm,
                                       float* __restrict__ SCR)
{
  // LN1 -> packed h2
  u64 h2[13];
  {
    float s = 0.f;
#pragma unroll
    for (int e = 0; e < 26; e++) s += x[e];
    float m = s * (1.f/26.f);
    float vv = 0.f;
#pragma unroll
    for (int e = 0; e < 26; e++){ float d = x[e]-m; vv += d*d; }
    float r = rsqrtf(vv*(1.f/26.f) + 1e-6f);
#pragma unroll
    for (int e = 0; e < 13; e++){
      float lo = (x[2*e]-m)*r*sm[OFF_LN1G+2*e]   + sm[OFF_LN1B+2*e];
      float hi = (x[2*e+1]-m)*r*sm[OFF_LN1G+2*e+1] + sm[OFF_LN1B+2*e+1];
      h2[e] = pack2(lo, hi);
    }
  }

  float ao[26];
#pragma unroll
  for (int head = 0; head < 2; head++){
    // q in registers (packed for score dots)
    float qd[13];
#pragma unroll
    for (int d = 0; d < 13; d++)
      qd[d] = sm[OFF_BQKV + head*13 + d]
            + dot26p(sm + OFF_WQKV + (head*13+d)*28, h2);
    u64 qp[6];
#pragma unroll
    for (int i = 0; i < 6; i++) qp[i] = pack2(qd[2*i], qd[2*i+1]);
    float q12 = qd[12];

    // k -> scratch
#pragma unroll 2
    for (int d = 0; d < 13; d++)
      SCR[lane*28 + d] = sm[OFF_BQKV + 26 + head*13 + d]
                       + dot26p(sm + OFF_WQKV + (26+head*13+d)*28, h2);
    __syncwarp(M25);

    // scores + softmax (row in registers)
    float p[25];
    float mx = -1e30f;
#pragma unroll
    for (int j = 0; j < 25; j++){
      float s = dot13p(SCR + j*28, qp, q12) * 0.2773500981126146f;  // 13^-0.5
      p[j] = s; mx = fmaxf(mx, s);
    }
    float se = 0.f;
#pragma unroll
    for (int j = 0; j < 25; j++){ float e2 = __expf(p[j]-mx); p[j] = e2; se += e2; }
    float inv = 1.f/se;
#pragma unroll
    for (int j = 0; j < 25; j++) p[j] *= inv;
    __syncwarp(M25);

    // v -> scratch
#pragma unroll 2
    for (int d = 0; d < 13; d++)
      SCR[lane*28 + d] = sm[OFF_BQKV + 52 + head*13 + d]
                       + dot26p(sm + OFF_WQKV + (52+head*13+d)*28, h2);
    __syncwarp(M25);

    // AV (packed accumulators)
    u64 oa[6];
#pragma unroll
    for (int i = 0; i < 6; i++) oa[i] = 0ull;
    float o12 = 0.f;
#pragma unroll
    for (int j = 0; j < 25; j++){
      const float* vr = SCR + j*28;
      const ulonglong2* v2 = (const ulonglong2*)vr;
      ulonglong2 a = v2[0], b = v2[1], c = v2[2];
      float pj = p[j];
      u64 pj2 = pack2(pj, pj);
      oa[0] = fma2(a.x, pj2, oa[0]); oa[1] = fma2(a.y, pj2, oa[1]);
      oa[2] = fma2(b.x, pj2, oa[2]); oa[3] = fma2(b.y, pj2, oa[3]);
      oa[4] = fma2(c.x, pj2, oa[4]); oa[5] = fma2(c.y, pj2, oa[5]);
      o12 += pj*vr[12];
    }
#pragma unroll
    for (int i = 0; i < 6; i++)
      unpack2(oa[i], ao[head*13 + 2*i], ao[head*13 + 2*i + 1]);
    ao[head*13 + 12] = o12;
    __syncwarp(M25);   // AV reads done before SCR is rewritten
  }

  // attn proj + residual (packed ao)
  {
    u64 ao2[13];
#pragma unroll
    for (int e = 0; e < 13; e++) ao2[e] = pack2(ao[2*e], ao[2*e+1]);
#pragma unroll
    for (int e = 0; e < 26; e++)
      x[e] += sm[OFF_BATT+e] + dot26p(sm + OFF_WATT + e*28, ao2);
  }

  // LN2 -> packed h2
  {
    float s = 0.f;
#pragma unroll
    for (int e = 0; e < 26; e++) s += x[e];
    float m = s * (1.f/26.f);
    float vv = 0.f;
#pragma unroll
    for (int e = 0; e < 26; e++){ float d = x[e]-m; vv += d*d; }
    float r = rsqrtf(vv*(1.f/26.f) + 1e-6f);
#pragma unroll
    for (int e = 0; e < 13; e++){
      float lo = (x[2*e]-m)*r*sm[OFF_LN2G+2*e]   + sm[OFF_LN2B+2*e];
      float hi = (x[2*e+1]-m)*r*sm[OFF_LN2G+2*e+1] + sm[OFF_LN2B+2*e+1];
      h2[e] = pack2(lo, hi);
    }
  }

  // fused FFN: packed residual accumulators
  {
    u64 xa[13];
#pragma unroll
    for (int e = 0; e < 13; e++)
      xa[e] = pack2(x[2*e] + sm[OFF_BFC2+2*e], x[2*e+1] + sm[OFF_BFC2+2*e+1]);
#pragma unroll 2
    for (int n = 0; n < 104; n++){
      float g = sm[OFF_BFC1+n] + dot26p(sm + OFF_WFC1 + n*28, h2);
      g = 0.5f*g*(1.f + erff(g*0.70710678118654752f));
      u64 g2 = pack2(g, g);
      const float* w2 = sm + OFF_WFC2T + n*28;
      const ulonglong2* w4 = (const ulonglong2*)w2;
      ulonglong2 a = w4[0], b = w4[1], c = w4[2];
      xa[0] = fma2(a.x, g2, xa[0]); xa[1] = fma2(a.y, g2, xa[1]);
      xa[2] = fma2(b.x, g2, xa[2]); xa[3] = fma2(b.y, g2, xa[3]);
      xa[4] = fma2(c.x, g2, xa[4]); xa[5] = fma2(c.y, g2, xa[5]);
      ulonglong2 d4 = w4[3], e4 = w4[4], f4 = w4[5];
      xa[6]  = fma2(d4.x, g2, xa[6]);  xa[7]  = fma2(d4.y, g2, xa[7]);
      xa[8]  = fma2(e4.x, g2, xa[8]);  xa[9]  = fma2(e4.y, g2, xa[9]);
      xa[10] = fma2(f4.x, g2, xa[10]); xa[11] = fma2(f4.y, g2, xa[11]);
      xa[12] = fma2(((const u64*)w2)[12], g2, xa[12]);
    }
#pragma unroll
    for (int e = 0; e < 13; e++) unpack2(xa[e], x[2*e], x[2*e+1]);
  }
}

// ---------------- main fused kernel: CTA = one query x 5 ways, warp per pair ----------
__global__ __launch_bounds__(BLK, 2) void pair_kernel(
    const float* __restrict__ pos_x, const float* __restrict__ pos_y,
    const float* __restrict__ ln1_g, const float* __restrict__ ln1_b,
    const float* __restrict__ qkv_w, const float* __restrict__ qkv_b,
    const float* __restrict__ attn_w, const float* __restrict__ attn_b,
    const float* __restrict__ ln2_g, const float* __restrict__ ln2_b,
    const float* __restrict__ fc1_w, const float* __restrict__ fc1_b,
    const float* __restrict__ fc2_w, const float* __restrict__ fc2_b,
    const float* __restrict__ dec_w, const float* __restrict__ dec_b,
    float* __restrict__ out)
{
  extern __shared__ float sm[];
  const int q = blockIdx.x;
  const int tid = threadIdx.x;

  // ---- stage weights / tiles ----
  for (int idx = tid; idx < 78*26; idx += BLK)  sm[OFF_WQKV + (idx/26)*28 + idx%26] = qkv_w[idx];
  for (int idx = tid; idx < 26*26; idx += BLK)  sm[OFF_WATT + (idx/26)*28 + idx%26] = attn_w[idx];
  for (int idx = tid; idx < 104*26; idx += BLK) sm[OFF_WFC1 + (idx/26)*28 + idx%26] = fc1_w[idx];
  for (int idx = tid; idx < 26*104; idx += BLK){ int e = idx/104, f = idx%104;
                                                 sm[OFF_WFC2T + f*28 + e] = fc2_w[idx]; }
  for (int idx = tid; idx < 25*26; idx += BLK)  sm[OFF_WDEC + (idx/26)*28 + idx%26] = dec_w[idx];
  if (tid < 78)  sm[OFF_BQKV+tid] = qkv_b[tid];
  if (tid < 104) sm[OFF_BFC1+tid] = fc1_b[tid];
  if (tid < 26){
    sm[OFF_BATT+tid] = attn_b[tid]; sm[OFF_BFC2+tid] = fc2_b[tid];
    sm[OFF_LN1G+tid] = ln1_g[tid];  sm[OFF_LN1B+tid] = ln1_b[tid];
    sm[OFF_LN2G+tid] = ln2_g[tid];  sm[OFF_LN2B+tid] = ln2_b[tid];
  }
  if (tid >= 32 && tid < 57) sm[OFF_BDEC + tid-32] = dec_b[tid-32];
  for (int idx = tid; idx < 650; idx += BLK){
    int p = idx/26, e = idx%26, px = p/5, py = p%5;
    sm[OFF_POS + p*27 + e] = (e < 13) ? pos_x[py*13 + e] : pos_y[px*13 + (e-13)];
  }
  for (int idx = tid; idx < 5*1600; idx += BLK){
    int w = idx/1600, r = idx%1600, c = r/25, i = r%25;
    sm[OFF_SN + w*1792 + c*28 + i] = g_sn[idx];
  }
  for (int idx = tid; idx < 1600; idx += BLK){
    int c = idx/25, j = idx%25;
    sm[OFF_QN + c*28 + j] = g_qn[q*1600 + idx];
  }
  for (int idx = tid; idx < 125; idx += BLK){ sm[OFF_RS+idx] = g_rs[idx]; sm[OFF_SP+idx] = g_sp[idx]; }
  if (tid >= 64 && tid < 89){ sm[OFF_RQ + tid-64] = g_rq[q*25 + tid-64];
                              sm[OFF_TP + tid-64] = g_tp[q*25 + tid-64]; }
  __syncthreads();

  const int w    = tid >> 5;
  const int lane = tid & 31;
  float* SNw   = sm + OFF_SN   + w*1792;
  float* SCR   = sm + OFF_SCR  + w*700;
  float* CORR  = sm + OFF_CORR + w*725;
  float* ATTSw = sm + OFF_ATTS + w*32;
  float* ATTQw = sm + OFF_ATTQ + w*32;

  if (lane < 25){
    // ---- corr (packed accumulators) ----
    u64 a2[12];
#pragma unroll
    for (int i = 0; i < 12; i++) a2[i] = 0ull;
    float a24 = 0.f;
    for (int c = 0; c < 64; c++){
      float qc = sm[OFF_QN + c*28 + lane];
      u64 qc2 = pack2(qc, qc);
      const float* srow = SNw + c*28;
      const ulonglong2* s2 = (const ulonglong2*)srow;
      ulonglong2 v0=s2[0], v1=s2[1], v2=s2[2], v3=s2[3], v4=s2[4], v5=s2[5];
      a2[0] = fma2(v0.x,qc2,a2[0]); a2[1] = fma2(v0.y,qc2,a2[1]);
      a2[2] = fma2(v1.x,qc2,a2[2]); a2[3] = fma2(v1.y,qc2,a2[3]);
      a2[4] = fma2(v2.x,qc2,a2[4]); a2[5] = fma2(v2.y,qc2,a2[5]);
      a2[6] = fma2(v3.x,qc2,a2[6]); a2[7] = fma2(v3.y,qc2,a2[7]);
      a2[8] = fma2(v4.x,qc2,a2[8]); a2[9] = fma2(v4.y,qc2,a2[9]);
      a2[10]= fma2(v5.x,qc2,a2[10]);a2[11]= fma2(v5.y,qc2,a2[11]);
      a24 += srow[24]*qc;
    }
    float rq = sm[OFF_RQ + lane];
    float acc[25];
#pragma unroll
    for (int i = 0; i < 12; i++) unpack2(a2[i], acc[2*i], acc[2*i+1]);
    acc[24] = a24;
#pragma unroll
    for (int i = 0; i < 25; i++)
      CORR[i*29 + lane] = acc[i] * sm[OFF_RS + w*25 + i] * rq;
    __syncwarp(M25);

    // ---- x1 ----
    float x[26];
#pragma unroll
    for (int e = 0; e < 25; e++) x[e] = CORR[e*29 + lane];
    x[25] = sm[OFF_TP + lane];
#pragma unroll
    for (int e = 0; e < 26; e++) x[e] += sm[OFF_POS + lane*27 + e];

    xblock(x, lane, sm, SCR);

    // dec1 -> SCR (packed x)
    {
      u64 x2[13];
#pragma unroll
      for (int e = 0; e < 13; e++) x2[e] = pack2(x[2*e], x[2*e+1]);
#pragma unroll 2
      for (int o = 0; o < 25; o++)
        SCR[lane*28 + o] = sm[OFF_BDEC+o] + dot26p(sm + OFF_WDEC + o*28, x2);
    }
    __syncwarp(M25);

    // ---- x2 ----
#pragma unroll
    for (int e = 0; e < 25; e++) x[e] = SCR[e*28 + lane] + CORR[lane*29 + e];
    x[25] = sm[OFF_SP + w*25 + lane];
#pragma unroll
    for (int e = 0; e < 26; e++) x[e] += sm[OFF_POS + lane*27 + e];
    __syncwarp(M25);

    xblock(x, lane, sm, SCR);

    // dec2 + refined row
    float y[25];
    {
      u64 x2[13];
#pragma unroll
      for (int e = 0; e < 13; e++) x2[e] = pack2(x[2*e], x[2*e+1]);
#pragma unroll 2
      for (int o = 0; o < 25; o++)
        y[o] = sm[OFF_BDEC+o] + dot26p(sm + OFF_WDEC + o*28, x2) + CORR[lane*29 + o];
    }
#pragma unroll
    for (int o = 0; o < 25; o++) CORR[lane*29 + o] = y[o];
    __syncwarp(M25);

    // ---- attn_q: row-wise gnorm + softmax ----
    {
      float s = 0.f;
#pragma unroll
      for (int j = 0; j < 25; j++) s += y[j];
      float m = s*(1.f/25.f);
      float vv = 0.f;
#pragma unroll
      for (int j = 0; j < 25; j++){ float d = y[j]-m; vv += d*d; }
      float inv = 0.2f * rsqrtf(vv*(1.f/24.f) + 1e-5f);
      float mx = -1e30f;
#pragma unroll
      for (int j = 0; j < 25; j++){ float z = (y[j]-m)*inv; y[j] = z; mx = fmaxf(mx, z); }
      float se = 0.f;
#pragma unroll
      for (int j = 0; j < 25; j++){ float e2 = __expf(y[j]-mx); y[j] = e2; se += e2; }
      float is = 1.f/se;
#pragma unroll
      for (int j = 0; j < 25; j++) SCR[lane*28 + j] = y[j]*is;
    }
    __syncwarp(M25);
    {
      float s = 0.f;
#pragma unroll
      for (int i = 0; i < 25; i++) s += SCR[i*28 + lane];
      ATTQw[lane] = s;
    }
    __syncwarp(M25);

    // ---- attn_s: column-wise gnorm + softmax ----
    {
      float col[25];
#pragma unroll
      for (int i = 0; i < 25; i++) col[i] = CORR[i*29 + lane];
      float s = 0.f;
#pragma unroll
      for (int i = 0; i < 25; i++) s += col[i];
      float m = s*(1.f/25.f);
      float vv = 0.f;
#pragma unroll
      for (int i = 0; i < 25; i++){ float d = col[i]-m; vv += d*d; }
      float inv = 0.2f * rsqrtf(vv*(1.f/24.f) + 1e-5f);
      float mx = -1e30f;
#pragma unroll
      for (int i = 0; i < 25; i++){ float z = (col[i]-m)*inv; col[i] = z; mx = fmaxf(mx, z); }
      float se = 0.f;
#pragma unroll
      for (int i = 0; i < 25; i++){ float e2 = __expf(col[i]-mx); col[i] = e2; se += e2; }
      float is = 1.f/se;
#pragma unroll
      for (int i = 0; i < 25; i++) SCR[i*28 + lane] = col[i]*is;
    }
    __syncwarp(M25);
    {
      float s = 0.f;
#pragma unroll
      for (int j = 0; j < 25; j++) s += SCR[lane*28 + j];
      ATTSw[lane] = s;
    }
  }
  __syncwarp();

  // ---- pooling + cosine sim ----
  {
    int c0 = lane, c1 = lane + 32;
    float sp0=0.f, sp1=0.f, qp0=0.f, qp1=0.f;
#pragma unroll
    for (int t = 0; t < 25; t++){
      float as_ = ATTSw[t], aq_ = ATTQw[t];
      sp0 += as_ * SNw[c0*28 + t];
      sp1 += as_ * SNw[c1*28 + t];
      qp0 += aq_ * sm[OFF_QN + c0*28 + t];
      qp1 += aq_ * sm[OFF_QN + c1*28 + t];
    }
    sp0 *= 0.04f; sp1 *= 0.04f; qp0 *= 0.04f; qp1 *= 0.04f;
    float dd = sp0*qp0 + sp1*qp1;
    float na = sp0*sp0 + sp1*sp1;
    float nb = qp0*qp0 + qp1*qp1;
#pragma unroll
    for (int off = 16; off; off >>= 1){
      dd += __shfl_xor_sync(0xFFFFFFFFu, dd, off);
      na += __shfl_xor_sync(0xFFFFFFFFu, na, off);
      nb += __shfl_xor_sync(0xFFFFFFFFu, nb, off);
    }
    if (lane == 0){
      float n1 = fmaxf(sqrtf(na), 1e-8f);
      float n2 = fmaxf(sqrtf(nb), 1e-8f);
      out[q*WAYv + w] = dd / (n1*n2) * 5.0f;
    }
  }
}

// ---------------- launch ----------------
extern "C" void kernel_launch(void* const* d_in, const int* in_sizes, int n_in,
                              void* d_out, int out_size)
{
  const float* spt    = (const float*)d_in[0];
  const float* qry    = (const float*)d_in[1];
  const float* proj_w = (const float*)d_in[2];
  const float* proj_b = (const float*)d_in[3];
  const float* pos_x  = (const float*)d_in[4];
  const float* pos_y  = (const float*)d_in[5];
  const float* ln1_g  = (const float*)d_in[6];
  const float* ln1_b  = (const float*)d_in[7];
  const float* qkv_w  = (const float*)d_in[8];
  const float* qkv_b  = (const float*)d_in[9];
  const float* attn_w = (const float*)d_in[10];
  const float* attn_b = (const float*)d_in[11];
  const float* ln2_g  = (const float*)d_in[12];
  const float* ln2_b  = (const float*)d_in[13];
  const float* fc1_w  = (const float*)d_in[14];
  const float* fc1_b  = (const float*)d_in[15];
  const float* fc2_w  = (const float*)d_in[16];
  const float* fc2_b  = (const float*)d_in[17];
  const float* dec_w  = (const float*)d_in[18];
  const float* dec_b  = (const float*)d_in[19];
  float* out = (float*)d_out;

  float *qn, *rq, *tp, *sn, *rs, *sp;
  cudaGetSymbolAddress((void**)&qn, g_qn);
  cudaGetSymbolAddress((void**)&rq, g_rq);
  cudaGetSymbolAddress((void**)&tp, g_tp);
  cudaGetSymbolAddress((void**)&sn, g_sn);
  cudaGetSymbolAddress((void**)&rs, g_rs);
  cudaGetSymbolAddress((void**)&sp, g_sp);

  prep_kernel<<<WAYv, 32>>>(spt, proj_w, proj_b, sn, rs, sp);
  prep_kernel<<<NQv, 32>>>(qry, proj_w, proj_b, qn, rq, tp);

  size_t shmem = SMEM_FLOATS * sizeof(float);
  static int configured = -1;
  if (configured < 0){
    cudaFuncSetAttribute(pair_kernel, cudaFuncAttributeMaxDynamicSharedMemorySize, (int)shmem);
    configured = 1;
  }
  pair_kernel<<<NQv, BLK, shmem>>>(
      pos_x, pos_y, ln1_g, ln1_b, qkv_w, qkv_b, attn_w, attn_b,
      ln2_g, ln2_b, fc1_w, fc1_b, fc2_w, fc2_b, dec_w, dec_b, out);
}

// round 5
// speedup vs baseline: 2.9218x; 1.6373x over previous
#include <cuda_runtime.h>
#include <math.h>

#define NQv 4096
#define WAYv 5
#define Cv 64
#define Tv 25
#define QPB 3                 // queries per CTA
#define BLK (QPB*WAYv*32)     // 480 threads = 15 warps

typedef unsigned long long u64;

// ---------------- f32x2 packed helpers ----------------
__device__ __forceinline__ u64 pack2(float lo, float hi){
  u64 r; asm("mov.b64 %0, {%1, %2};" : "=l"(r) : "f"(lo), "f"(hi)); return r;
}
__device__ __forceinline__ void unpack2(u64 v, float& lo, float& hi){
  asm("mov.b64 {%0, %1}, %2;" : "=f"(lo), "=f"(hi) : "l"(v));
}
__device__ __forceinline__ u64 fma2(u64 a, u64 b, u64 c){
  u64 d; asm("fma.rn.f32x2 %0, %1, %2, %3;" : "=l"(d) : "l"(a), "l"(b), "l"(c)); return d;
}

// ---------------- global scratch (pair-independent precompute) ----------------
__device__ float g_qn[NQv*Cv*Tv];
__device__ float g_rq[NQv*Tv];
__device__ float g_tp[NQv*Tv];
__device__ float g_sn[WAYv*Cv*Tv];
__device__ float g_rs[WAYv*Tv];
__device__ float g_sp[WAYv*Tv];

// ---------------- shared layout (floats), 16B-aligned vector regions first ----------
enum {
  OFF_WQKV = 0,                       // 78 x 28
  OFF_WATT = OFF_WQKV + 78*28,        // 26 x 28
  OFF_WFC1 = OFF_WATT + 26*28,        // 104 x 28
  OFF_WFC2T= OFF_WFC1 + 104*28,       // 104 x 28 (fc2 transposed)
  OFF_WDEC = OFF_WFC2T + 104*28,      // 25 x 28
  OFF_SN   = OFF_WDEC + 25*28,        // 5 x 64 x 28      (per way)
  OFF_QN   = OFF_SN + 5*64*28,        // QPB x 64 x 28    (per query)
  OFF_SCR  = OFF_QN + QPB*64*28,      // 15 x 25 x 28     (per warp)
  OFF_CORR = OFF_SCR + QPB*5*700,     // 15 x 25 x 29     (per warp)
  OFF_BQKV = OFF_CORR + QPB*5*725,
  OFF_BATT = OFF_BQKV + 78,
  OFF_BFC1 = OFF_BATT + 26,
  OFF_BFC2 = OFF_BFC1 + 104,
  OFF_BDEC = OFF_BFC2 + 26,
  OFF_LN1G = OFF_BDEC + 25,
  OFF_LN1B = OFF_LN1G + 26,
  OFF_LN2G = OFF_LN1B + 26,
  OFF_LN2B = OFF_LN2G + 26,
  OFF_POS  = OFF_LN2B + 26,           // 25 x 27
  OFF_RS   = OFF_POS + 25*27,         // 5 x 25
  OFF_SP   = OFF_RS + 125,            // 5 x 25
  OFF_RQ   = OFF_SP + 125,            // QPB x 25
  OFF_TP   = OFF_RQ + QPB*25,         // QPB x 25
  OFF_ATTS = OFF_TP + QPB*25,         // 15 x 32
  OFF_ATTQ = OFF_ATTS + QPB*5*32,     // 15 x 32
  SMEM_FLOATS = OFF_ATTQ + QPB*5*32
};

// ---------------- prep ----------------
__global__ void prep_kernel(const float* __restrict__ in,
                            const float* __restrict__ pw,
                            const float* __restrict__ pb,
                            float* __restrict__ on,
                            float* __restrict__ orr,
                            float* __restrict__ op)
{
  int img = blockIdx.x;
  int t = threadIdx.x;
  if (t >= Tv) return;
  const float* base = in + img*Cv*Tv;
  float v[Cv];
  float s = 0.f;
#pragma unroll
  for (int c = 0; c < Cv; c++){ v[c] = base[c*Tv + t]; s += v[c]; }
  float m = s * (1.f/64.f);
  float ss0=0.f, ss1=0.f, pj0=0.f, pj1=0.f;
#pragma unroll
  for (int c = 0; c < Cv; c += 2){
    float d0 = v[c]-m, d1 = v[c+1]-m;
    on[img*Cv*Tv + c*Tv + t]     = d0;
    on[img*Cv*Tv + (c+1)*Tv + t] = d1;
    ss0 += d0*d0; ss1 += d1*d1;
    pj0 += d0*pw[c]; pj1 += d1*pw[c+1];
  }
  orr[img*Tv + t] = rsqrtf(ss0+ss1 + 1e-6f);
  op[img*Tv + t]  = pj0+pj1 + pb[0];
}

// ---------------- packed dot helpers ----------------
__device__ __forceinline__ float dot26p(const float* __restrict__ row, const u64 (&h2)[13]){
  const ulonglong2* r2 = (const ulonglong2*)row;
  u64 a0 = 0ull, a1 = 0ull;
  ulonglong2 v0 = r2[0], v1 = r2[1], v2 = r2[2];
  a0 = fma2(v0.x, h2[0], a0);  a1 = fma2(v0.y, h2[1], a1);
  a0 = fma2(v1.x, h2[2], a0);  a1 = fma2(v1.y, h2[3], a1);
  a0 = fma2(v2.x, h2[4], a0);  a1 = fma2(v2.y, h2[5], a1);
  ulonglong2 v3 = r2[3], v4 = r2[4], v5 = r2[5];
  a0 = fma2(v3.x, h2[6], a0);  a1 = fma2(v3.y, h2[7], a1);
  a0 = fma2(v4.x, h2[8], a0);  a1 = fma2(v4.y, h2[9], a1);
  a0 = fma2(v5.x, h2[10], a0); a1 = fma2(v5.y, h2[11], a1);
  a0 = fma2(((const u64*)row)[12], h2[12], a0);
  float l0,hh0,l1,hh1;
  unpack2(a0,l0,hh0); unpack2(a1,l1,hh1);
  return (l0+hh0)+(l1+hh1);
}

__device__ __forceinline__ float dot13p(const float* __restrict__ row,
                                        const u64 (&qp)[6], float q12){
  const ulonglong2* r2 = (const ulonglong2*)row;
  ulonglong2 v0 = r2[0], v1 = r2[1], v2 = r2[2];
  u64 a0 = 0ull, a1 = 0ull;
  a0 = fma2(v0.x, qp[0], a0); a1 = fma2(v0.y, qp[1], a1);
  a0 = fma2(v1.x, qp[2], a0); a1 = fma2(v1.y, qp[3], a1);
  a0 = fma2(v2.x, qp[4], a0); a1 = fma2(v2.y, qp[5], a1);
  float l0,hh0,l1,hh1;
  unpack2(a0,l0,hh0); unpack2(a1,l1,hh1);
  return (l0+hh0)+(l1+hh1) + q12*row[12];
}

#define M25 0x01FFFFFFu

// ---------------- pre-LN transformer block, packed activations ----------------
__device__ __forceinline__ void xblock(float (&x)[26], int lane, float* __restrict__ sm,
                                       float* __restrict__ SCR)
{
  // LN1 -> packed h2
  u64 h2[13];
  {
    float s = 0.f;
#pragma unroll
    for (int e = 0; e < 26; e++) s += x[e];
    float m = s * (1.f/26.f);
    float vv = 0.f;
#pragma unroll
    for (int e = 0; e < 26; e++){ float d = x[e]-m; vv += d*d; }
    float r = rsqrtf(vv*(1.f/26.f) + 1e-6f);
#pragma unroll
    for (int e = 0; e < 13; e++){
      float lo = (x[2*e]-m)*r*sm[OFF_LN1G+2*e]   + sm[OFF_LN1B+2*e];
      float hi = (x[2*e+1]-m)*r*sm[OFF_LN1G+2*e+1] + sm[OFF_LN1B+2*e+1];
      h2[e] = pack2(lo, hi);
    }
  }

  float ao[26];
#pragma unroll
  for (int head = 0; head < 2; head++){
    float qd[13];
#pragma unroll
    for (int d = 0; d < 13; d++)
      qd[d] = sm[OFF_BQKV + head*13 + d]
            + dot26p(sm + OFF_WQKV + (head*13+d)*28, h2);
    u64 qp[6];
#pragma unroll
    for (int i = 0; i < 6; i++) qp[i] = pack2(qd[2*i], qd[2*i+1]);
    float q12 = qd[12];

#pragma unroll 2
    for (int d = 0; d < 13; d++)
      SCR[lane*28 + d] = sm[OFF_BQKV + 26 + head*13 + d]
                       + dot26p(sm + OFF_WQKV + (26+head*13+d)*28, h2);
    __syncwarp(M25);

    float p[25];
    float mx = -1e30f;
#pragma unroll
    for (int j = 0; j < 25; j++){
      float s = dot13p(SCR + j*28, qp, q12) * 0.2773500981126146f;
      p[j] = s; mx = fmaxf(mx, s);
    }
    float se = 0.f;
#pragma unroll
    for (int j = 0; j < 25; j++){ float e2 = __expf(p[j]-mx); p[j] = e2; se += e2; }
    float inv = 1.f/se;
#pragma unroll
    for (int j = 0; j < 25; j++) p[j] *= inv;
    __syncwarp(M25);

#pragma unroll 2
    for (int d = 0; d < 13; d++)
      SCR[lane*28 + d] = sm[OFF_BQKV + 52 + head*13 + d]
                       + dot26p(sm + OFF_WQKV + (52+head*13+d)*28, h2);
    __syncwarp(M25);

    u64 oa[6];
#pragma unroll
    for (int i = 0; i < 6; i++) oa[i] = 0ull;
    float o12 = 0.f;
#pragma unroll
    for (int j = 0; j < 25; j++){
      const float* vr = SCR + j*28;
      const ulonglong2* v2 = (const ulonglong2*)vr;
      ulonglong2 a = v2[0], b = v2[1], c = v2[2];
      float pj = p[j];
      u64 pj2 = pack2(pj, pj);
      oa[0] = fma2(a.x, pj2, oa[0]); oa[1] = fma2(a.y, pj2, oa[1]);
      oa[2] = fma2(b.x, pj2, oa[2]); oa[3] = fma2(b.y, pj2, oa[3]);
      oa[4] = fma2(c.x, pj2, oa[4]); oa[5] = fma2(c.y, pj2, oa[5]);
      o12 += pj*vr[12];
    }
#pragma unroll
    for (int i = 0; i < 6; i++)
      unpack2(oa[i], ao[head*13 + 2*i], ao[head*13 + 2*i + 1]);
    ao[head*13 + 12] = o12;
    __syncwarp(M25);
  }

  // attn proj + residual
  {
    u64 ao2[13];
#pragma unroll
    for (int e = 0; e < 13; e++) ao2[e] = pack2(ao[2*e], ao[2*e+1]);
#pragma unroll
    for (int e = 0; e < 26; e++)
      x[e] += sm[OFF_BATT+e] + dot26p(sm + OFF_WATT + e*28, ao2);
  }

  // LN2 -> packed h2
  {
    float s = 0.f;
#pragma unroll
    for (int e = 0; e < 26; e++) s += x[e];
    float m = s * (1.f/26.f);
    float vv = 0.f;
#pragma unroll
    for (int e = 0; e < 26; e++){ float d = x[e]-m; vv += d*d; }
    float r = rsqrtf(vv*(1.f/26.f) + 1e-6f);
#pragma unroll
    for (int e = 0; e < 13; e++){
      float lo = (x[2*e]-m)*r*sm[OFF_LN2G+2*e]   + sm[OFF_LN2B+2*e];
      float hi = (x[2*e+1]-m)*r*sm[OFF_LN2G+2*e+1] + sm[OFF_LN2B+2*e+1];
      h2[e] = pack2(lo, hi);
    }
  }

  // fused FFN
  {
    u64 xa[13];
#pragma unroll
    for (int e = 0; e < 13; e++)
      xa[e] = pack2(x[2*e] + sm[OFF_BFC2+2*e], x[2*e+1] + sm[OFF_BFC2+2*e+1]);
#pragma unroll 2
    for (int n = 0; n < 104; n++){
      float g = sm[OFF_BFC1+n] + dot26p(sm + OFF_WFC1 + n*28, h2);
      g = 0.5f*g*(1.f + erff(g*0.70710678118654752f));
      u64 g2 = pack2(g, g);
      const float* w2 = sm + OFF_WFC2T + n*28;
      const ulonglong2* w4 = (const ulonglong2*)w2;
      ulonglong2 a = w4[0], b = w4[1], c = w4[2];
      xa[0] = fma2(a.x, g2, xa[0]); xa[1] = fma2(a.y, g2, xa[1]);
      xa[2] = fma2(b.x, g2, xa[2]); xa[3] = fma2(b.y, g2, xa[3]);
      xa[4] = fma2(c.x, g2, xa[4]); xa[5] = fma2(c.y, g2, xa[5]);
      ulonglong2 d4 = w4[3], e4 = w4[4], f4 = w4[5];
      xa[6]  = fma2(d4.x, g2, xa[6]);  xa[7]  = fma2(d4.y, g2, xa[7]);
      xa[8]  = fma2(e4.x, g2, xa[8]);  xa[9]  = fma2(e4.y, g2, xa[9]);
      xa[10] = fma2(f4.x, g2, xa[10]); xa[11] = fma2(f4.y, g2, xa[11]);
      xa[12] = fma2(((const u64*)w2)[12], g2, xa[12]);
    }
#pragma unroll
    for (int e = 0; e < 13; e++) unpack2(xa[e], x[2*e], x[2*e+1]);
  }
}

// ---------------- main fused kernel: CTA = QPB queries x 5 ways, warp per pair ------
__global__ __launch_bounds__(BLK, 1) void pair_kernel(
    const float* __restrict__ pos_x, const float* __restrict__ pos_y,
    const float* __restrict__ ln1_g, const float* __restrict__ ln1_b,
    const float* __restrict__ qkv_w, const float* __restrict__ qkv_b,
    const float* __restrict__ attn_w, const float* __restrict__ attn_b,
    const float* __restrict__ ln2_g, const float* __restrict__ ln2_b,
    const float* __restrict__ fc1_w, const float* __restrict__ fc1_b,
    const float* __restrict__ fc2_w, const float* __restrict__ fc2_b,
    const float* __restrict__ dec_w, const float* __restrict__ dec_b,
    float* __restrict__ out)
{
  extern __shared__ float sm[];
  const int q0 = blockIdx.x * QPB;
  const int tid = threadIdx.x;

  // ---- stage weights (shared by all 15 warps) ----
  for (int idx = tid; idx < 78*26; idx += BLK)  sm[OFF_WQKV + (idx/26)*28 + idx%26] = qkv_w[idx];
  for (int idx = tid; idx < 26*26; idx += BLK)  sm[OFF_WATT + (idx/26)*28 + idx%26] = attn_w[idx];
  for (int idx = tid; idx < 104*26; idx += BLK) sm[OFF_WFC1 + (idx/26)*28 + idx%26] = fc1_w[idx];
  for (int idx = tid; idx < 26*104; idx += BLK){ int e = idx/104, f = idx%104;
                                                 sm[OFF_WFC2T + f*28 + e] = fc2_w[idx]; }
  for (int idx = tid; idx < 25*26; idx += BLK)  sm[OFF_WDEC + (idx/26)*28 + idx%26] = dec_w[idx];
  if (tid < 78)  sm[OFF_BQKV+tid] = qkv_b[tid];
  if (tid < 104) sm[OFF_BFC1+tid] = fc1_b[tid];
  if (tid < 26){
    sm[OFF_BATT+tid] = attn_b[tid]; sm[OFF_BFC2+tid] = fc2_b[tid];
    sm[OFF_LN1G+tid] = ln1_g[tid];  sm[OFF_LN1B+tid] = ln1_b[tid];
    sm[OFF_LN2G+tid] = ln2_g[tid];  sm[OFF_LN2B+tid] = ln2_b[tid];
  }
  if (tid >= 32 && tid < 57) sm[OFF_BDEC + tid-32] = dec_b[tid-32];
  for (int idx = tid; idx < 650; idx += BLK){
    int p = idx/26, e = idx%26, px = p/5, py = p%5;
    sm[OFF_POS + p*27 + e] = (e < 13) ? pos_x[py*13 + e] : pos_y[px*13 + (e-13)];
  }
  for (int idx = tid; idx < 5*1600; idx += BLK){
    int ww = idx/1600, r = idx%1600, c = r/25, i = r%25;
    sm[OFF_SN + ww*1792 + c*28 + i] = g_sn[idx];
  }
  for (int idx = tid; idx < QPB*1600; idx += BLK){
    int sq = idx/1600, r = idx%1600, c = r/25, j = r%25;
    int qq = q0 + sq;
    if (qq < NQv) sm[OFF_QN + sq*1792 + c*28 + j] = g_qn[qq*1600 + r];
  }
  for (int idx = tid; idx < 125; idx += BLK){ sm[OFF_RS+idx] = g_rs[idx]; sm[OFF_SP+idx] = g_sp[idx]; }
  for (int idx = tid; idx < QPB*25; idx += BLK){
    int sq = idx/25, j = idx%25, qq = q0 + sq;
    if (qq < NQv){ sm[OFF_RQ + sq*25 + j] = g_rq[qq*25 + j];
                   sm[OFF_TP + sq*25 + j] = g_tp[qq*25 + j]; }
  }
  __syncthreads();

  const int wid  = tid >> 5;            // 0..14
  const int subq = wid / WAYv;          // query within CTA
  const int w    = wid - subq*WAYv;     // way
  const int lane = tid & 31;
  const int q    = q0 + subq;
  if (q >= NQv) return;

  float* SNw   = sm + OFF_SN   + w*1792;
  float* QNq   = sm + OFF_QN   + subq*1792;
  float* SCR   = sm + OFF_SCR  + wid*700;
  float* CORR  = sm + OFF_CORR + wid*725;
  float* ATTSw = sm + OFF_ATTS + wid*32;
  float* ATTQw = sm + OFF_ATTQ + wid*32;
  const float* RQq = sm + OFF_RQ + subq*25;
  const float* TPq = sm + OFF_TP + subq*25;

  if (lane < 25){
    // ---- corr (packed accumulators) ----
    u64 a2[12];
#pragma unroll
    for (int i = 0; i < 12; i++) a2[i] = 0ull;
    float a24 = 0.f;
    for (int c = 0; c < 64; c++){
      float qc = QNq[c*28 + lane];
      u64 qc2 = pack2(qc, qc);
      const float* srow = SNw + c*28;
      const ulonglong2* s2 = (const ulonglong2*)srow;
      ulonglong2 v0=s2[0], v1=s2[1], v2=s2[2], v3=s2[3], v4=s2[4], v5=s2[5];
      a2[0] = fma2(v0.x,qc2,a2[0]); a2[1] = fma2(v0.y,qc2,a2[1]);
      a2[2] = fma2(v1.x,qc2,a2[2]); a2[3] = fma2(v1.y,qc2,a2[3]);
      a2[4] = fma2(v2.x,qc2,a2[4]); a2[5] = fma2(v2.y,qc2,a2[5]);
      a2[6] = fma2(v3.x,qc2,a2[6]); a2[7] = fma2(v3.y,qc2,a2[7]);
      a2[8] = fma2(v4.x,qc2,a2[8]); a2[9] = fma2(v4.y,qc2,a2[9]);
      a2[10]= fma2(v5.x,qc2,a2[10]);a2[11]= fma2(v5.y,qc2,a2[11]);
      a24 += srow[24]*qc;
    }
    float rq = RQq[lane];
    float acc[25];
#pragma unroll
    for (int i = 0; i < 12; i++) unpack2(a2[i], acc[2*i], acc[2*i+1]);
    acc[24] = a24;
#pragma unroll
    for (int i = 0; i < 25; i++)
      CORR[i*29 + lane] = acc[i] * sm[OFF_RS + w*25 + i] * rq;
    __syncwarp(M25);

    // ---- x1 ----
    float x[26];
#pragma unroll
    for (int e = 0; e < 25; e++) x[e] = CORR[e*29 + lane];
    x[25] = TPq[lane];
#pragma unroll
    for (int e = 0; e < 26; e++) x[e] += sm[OFF_POS + lane*27 + e];

    xblock(x, lane, sm, SCR);

    // dec1 -> SCR
    {
      u64 x2[13];
#pragma unroll
      for (int e = 0; e < 13; e++) x2[e] = pack2(x[2*e], x[2*e+1]);
#pragma unroll 2
      for (int o = 0; o < 25; o++)
        SCR[lane*28 + o] = sm[OFF_BDEC+o] + dot26p(sm + OFF_WDEC + o*28, x2);
    }
    __syncwarp(M25);

    // ---- x2 ----
#pragma unroll
    for (int e = 0; e < 25; e++) x[e] = SCR[e*28 + lane] + CORR[lane*29 + e];
    x[25] = sm[OFF_SP + w*25 + lane];
#pragma unroll
    for (int e = 0; e < 26; e++) x[e] += sm[OFF_POS + lane*27 + e];
    __syncwarp(M25);

    xblock(x, lane, sm, SCR);

    // dec2 + refined row
    float y[25];
    {
      u64 x2[13];
#pragma unroll
      for (int e = 0; e < 13; e++) x2[e] = pack2(x[2*e], x[2*e+1]);
#pragma unroll 2
      for (int o = 0; o < 25; o++)
        y[o] = sm[OFF_BDEC+o] + dot26p(sm + OFF_WDEC + o*28, x2) + CORR[lane*29 + o];
    }
#pragma unroll
    for (int o = 0; o < 25; o++) CORR[lane*29 + o] = y[o];
    __syncwarp(M25);

    // ---- attn_q ----
    {
      float s = 0.f;
#pragma unroll
      for (int j = 0; j < 25; j++) s += y[j];
      float m = s*(1.f/25.f);
      float vv = 0.f;
#pragma unroll
      for (int j = 0; j < 25; j++){ float d = y[j]-m; vv += d*d; }
      float inv = 0.2f * rsqrtf(vv*(1.f/24.f) + 1e-5f);
      float mx = -1e30f;
#pragma unroll
      for (int j = 0; j < 25; j++){ float z = (y[j]-m)*inv; y[j] = z; mx = fmaxf(mx, z); }
      float se = 0.f;
#pragma unroll
      for (int j = 0; j < 25; j++){ float e2 = __expf(y[j]-mx); y[j] = e2; se += e2; }
      float is = 1.f/se;
#pragma unroll
      for (int j = 0; j < 25; j++) SCR[lane*28 + j] = y[j]*is;
    }
    __syncwarp(M25);
    {
      float s = 0.f;
#pragma unroll
      for (int i = 0; i < 25; i++) s += SCR[i*28 + lane];
      ATTQw[lane] = s;
    }
    __syncwarp(M25);

    // ---- attn_s ----
    {
      float col[25];
#pragma unroll
      for (int i = 0; i < 25; i++) col[i] = CORR[i*29 + lane];
      float s = 0.f;
#pragma unroll
      for (int i = 0; i < 25; i++) s += col[i];
      float m = s*(1.f/25.f);
      float vv = 0.f;
#pragma unroll
      for (int i = 0; i < 25; i++){ float d = col[i]-m; vv += d*d; }
      float inv = 0.2f * rsqrtf(vv*(1.f/24.f) + 1e-5f);
      float mx = -1e30f;
#pragma unroll
      for (int i = 0; i < 25; i++){ float z = (col[i]-m)*inv; col[i] = z; mx = fmaxf(mx, z); }
      float se = 0.f;
#pragma unroll
      for (int i = 0; i < 25; i++){ float e2 = __expf(col[i]-mx); col[i] = e2; se += e2; }
      float is = 1.f/se;
#pragma unroll
      for (int i = 0; i < 25; i++) SCR[i*28 + lane] = col[i]*is;
    }
    __syncwarp(M25);
    {
      float s = 0.f;
#pragma unroll
      for (int j = 0; j < 25; j++) s += SCR[lane*28 + j];
      ATTSw[lane] = s;
    }
  }
  __syncwarp();

  // ---- pooling + cosine sim ----
  {
    int c0 = lane, c1 = lane + 32;
    float sp0=0.f, sp1=0.f, qp0=0.f, qp1=0.f;
#pragma unroll
    for (int t = 0; t < 25; t++){
      float as_ = ATTSw[t], aq_ = ATTQw[t];
      sp0 += as_ * SNw[c0*28 + t];
      sp1 += as_ * SNw[c1*28 + t];
      qp0 += aq_ * QNq[c0*28 + t];
      qp1 += aq_ * QNq[c1*28 + t];
    }
    sp0 *= 0.04f; sp1 *= 0.04f; qp0 *= 0.04f; qp1 *= 0.04f;
    float dd = sp0*qp0 + sp1*qp1;
    float na = sp0*sp0 + sp1*sp1;
    float nb = qp0*qp0 + qp1*qp1;
#pragma unroll
    for (int off = 16; off; off >>= 1){
      dd += __shfl_xor_sync(0xFFFFFFFFu, dd, off);
      na += __shfl_xor_sync(0xFFFFFFFFu, na, off);
      nb += __shfl_xor_sync(0xFFFFFFFFu, nb, off);
    }
    if (lane == 0){
      float n1 = fmaxf(sqrtf(na), 1e-8f);
      float n2 = fmaxf(sqrtf(nb), 1e-8f);
      out[q*WAYv + w] = dd / (n1*n2) * 5.0f;
    }
  }
}

// ---------------- launch ----------------
extern "C" void kernel_launch(void* const* d_in, const int* in_sizes, int n_in,
                              void* d_out, int out_size)
{
  const float* spt    = (const float*)d_in[0];
  const float* qry    = (const float*)d_in[1];
  const float* proj_w = (const float*)d_in[2];
  const float* proj_b = (const float*)d_in[3];
  const float* pos_x  = (const float*)d_in[4];
  const float* pos_y  = (const float*)d_in[5];
  const float* ln1_g  = (const float*)d_in[6];
  const float* ln1_b  = (const float*)d_in[7];
  const float* qkv_w  = (const float*)d_in[8];
  const float* qkv_b  = (const float*)d_in[9];
  const float* attn_w = (const float*)d_in[10];
  const float* attn_b = (const float*)d_in[11];
  const float* ln2_g  = (const float*)d_in[12];
  const float* ln2_b  = (const float*)d_in[13];
  const float* fc1_w  = (const float*)d_in[14];
  const float* fc1_b  = (const float*)d_in[15];
  const float* fc2_w  = (const float*)d_in[16];
  const float* fc2_b  = (const float*)d_in[17];
  const float* dec_w  = (const float*)d_in[18];
  const float* dec_b  = (const float*)d_in[19];
  float* out = (float*)d_out;

  float *qn, *rq, *tp, *sn, *rs, *sp;
  cudaGetSymbolAddress((void**)&qn, g_qn);
  cudaGetSymbolAddress((void**)&rq, g_rq);
  cudaGetSymbolAddress((void**)&tp, g_tp);
  cudaGetSymbolAddress((void**)&sn, g_sn);
  cudaGetSymbolAddress((void**)&rs, g_rs);
  cudaGetSymbolAddress((void**)&sp, g_sp);

  prep_kernel<<<WAYv, 32>>>(spt, proj_w, proj_b, sn, rs, sp);
  prep_kernel<<<NQv, 32>>>(qry, proj_w, proj_b, qn, rq, tp);

  size_t shmem = SMEM_FLOATS * sizeof(float);
  static int configured = -1;
  if (configured < 0){
    cudaFuncSetAttribute(pair_kernel, cudaFuncAttributeMaxDynamicSharedMemorySize, (int)shmem);
    configured = 1;
  }
  int grid = (NQv + QPB - 1) / QPB;
  pair_kernel<<<grid, BLK, shmem>>>(
      pos_x, pos_y, ln1_g, ln1_b, qkv_w, qkv_b, attn_w, attn_b,
      ln2_g, ln2_b, fc1_w, fc1_b, fc2_w, fc2_b, dec_w, dec_b, out);
}

// round 10
// speedup vs baseline: 3.1185x; 1.0673x over previous
#include <cuda_runtime.h>
#include <math.h>

#define NQv 4096
#define WAYv 5
#define Cv 64
#define Tv 25
#define QPB 4                 // queries per CTA (4096 % 4 == 0)
#define BLK (QPB*WAYv*32)     // 640 threads = 20 warps

typedef unsigned long long u64;

// ---------------- f32x2 packed helpers ----------------
__device__ __forceinline__ u64 pack2(float lo, float hi){
  u64 r; asm("mov.b64 %0, {%1, %2};" : "=l"(r) : "f"(lo), "f"(hi)); return r;
}
__device__ __forceinline__ void unpack2(u64 v, float& lo, float& hi){
  asm("mov.b64 {%0, %1}, %2;" : "=f"(lo), "=f"(hi) : "l"(v));
}
__device__ __forceinline__ u64 fma2(u64 a, u64 b, u64 c){
  u64 d; asm("fma.rn.f32x2 %0, %1, %2, %3;" : "=l"(d) : "l"(a), "l"(b), "l"(c)); return d;
}

// ---------------- global scratch (pair-independent precompute) ----------------
__device__ float g_qn[NQv*Cv*Tv];
__device__ float g_rq[NQv*Tv];
__device__ float g_tp[NQv*Tv];
__device__ float g_sn[WAYv*Cv*Tv];
__device__ float g_rs[WAYv*Tv];
__device__ float g_sp[WAYv*Tv];

// ---------------- shared layout (floats), 16B-aligned vector regions first ----------
enum {
  OFF_WQKV = 0,                       // 78 x 28
  OFF_WATT = OFF_WQKV + 78*28,        // 26 x 28
  OFF_WFC1 = OFF_WATT + 26*28,        // 104 x 28
  OFF_WFC2T= OFF_WFC1 + 104*28,       // 104 x 28 (fc2 transposed)
  OFF_WDEC = OFF_WFC2T + 104*28,      // 25 x 28
  OFF_SN   = OFF_WDEC + 25*28,        // 5 x 64 x 28      (per way)
  OFF_QN   = OFF_SN + 5*64*28,        // QPB x 64 x 28    (per query)
  OFF_SCR  = OFF_QN + QPB*64*28,      // 20 x 25 x 28     (per warp)
  OFF_CORR = OFF_SCR + QPB*5*700,     // 20 x 25 x 29     (per warp)
  OFF_BQKV = OFF_CORR + QPB*5*725,
  OFF_BATT = OFF_BQKV + 78,
  OFF_BFC1 = OFF_BATT + 26,
  OFF_BFC2 = OFF_BFC1 + 104,
  OFF_BDEC = OFF_BFC2 + 26,
  OFF_LN1G = OFF_BDEC + 25,
  OFF_LN1B = OFF_LN1G + 26,
  OFF_LN2G = OFF_LN1B + 26,
  OFF_LN2B = OFF_LN2G + 26,
  OFF_POS  = OFF_LN2B + 26,           // 25 x 27
  OFF_RS   = OFF_POS + 25*27,         // 5 x 25
  OFF_SP   = OFF_RS + 125,            // 5 x 25
  OFF_RQ   = OFF_SP + 125,            // QPB x 25
  OFF_TP   = OFF_RQ + QPB*25,         // QPB x 25
  OFF_ATTS = OFF_TP + QPB*25,         // 20 x 32
  OFF_ATTQ = OFF_ATTS + QPB*5*32,     // 20 x 32
  SMEM_FLOATS = OFF_ATTQ + QPB*5*32   // 56832 floats = 227328 B
};

// ---------------- prep ----------------
__global__ void prep_kernel(const float* __restrict__ in,
                            const float* __restrict__ pw,
                            const float* __restrict__ pb,
                            float* __restrict__ on,
                            float* __restrict__ orr,
                            float* __restrict__ op)
{
  int img = blockIdx.x;
  int t = threadIdx.x;
  if (t >= Tv) return;
  const float* base = in + img*Cv*Tv;
  float v[Cv];
  float s = 0.f;
#pragma unroll
  for (int c = 0; c < Cv; c++){ v[c] = base[c*Tv + t]; s += v[c]; }
  float m = s * (1.f/64.f);
  float ss0=0.f, ss1=0.f, pj0=0.f, pj1=0.f;
#pragma unroll
  for (int c = 0; c < Cv; c += 2){
    float d0 = v[c]-m, d1 = v[c+1]-m;
    on[img*Cv*Tv + c*Tv + t]     = d0;
    on[img*Cv*Tv + (c+1)*Tv + t] = d1;
    ss0 += d0*d0; ss1 += d1*d1;
    pj0 += d0*pw[c]; pj1 += d1*pw[c+1];
  }
  orr[img*Tv + t] = rsqrtf(ss0+ss1 + 1e-6f);
  op[img*Tv + t]  = pj0+pj1 + pb[0];
}

// ---------------- packed dot helpers ----------------
__device__ __forceinline__ float dot26p(const float* __restrict__ row, const u64 (&h2)[13]){
  const ulonglong2* r2 = (const ulonglong2*)row;
  u64 a0 = 0ull, a1 = 0ull;
  ulonglong2 v0 = r2[0], v1 = r2[1], v2 = r2[2];
  a0 = fma2(v0.x, h2[0], a0);  a1 = fma2(v0.y, h2[1], a1);
  a0 = fma2(v1.x, h2[2], a0);  a1 = fma2(v1.y, h2[3], a1);
  a0 = fma2(v2.x, h2[4], a0);  a1 = fma2(v2.y, h2[5], a1);
  ulonglong2 v3 = r2[3], v4 = r2[4], v5 = r2[5];
  a0 = fma2(v3.x, h2[6], a0);  a1 = fma2(v3.y, h2[7], a1);
  a0 = fma2(v4.x, h2[8], a0);  a1 = fma2(v4.y, h2[9], a1);
  a0 = fma2(v5.x, h2[10], a0); a1 = fma2(v5.y, h2[11], a1);
  a0 = fma2(((const u64*)row)[12], h2[12], a0);
  float l0,hh0,l1,hh1;
  unpack2(a0,l0,hh0); unpack2(a1,l1,hh1);
  return (l0+hh0)+(l1+hh1);
}

__device__ __forceinline__ float dot13p(const float* __restrict__ row,
                                        const u64 (&qp)[6], float q12){
  const ulonglong2* r2 = (const ulonglong2*)row;
  ulonglong2 v0 = r2[0], v1 = r2[1], v2 = r2[2];
  u64 a0 = 0ull, a1 = 0ull;
  a0 = fma2(v0.x, qp[0], a0); a1 = fma2(v0.y, qp[1], a1);
  a0 = fma2(v1.x, qp[2], a0); a1 = fma2(v1.y, qp[3], a1);
  a0 = fma2(v2.x, qp[4], a0); a1 = fma2(v2.y, qp[5], a1);
  float l0,hh0,l1,hh1;
  unpack2(a0,l0,hh0); unpack2(a1,l1,hh1);
  return (l0+hh0)+(l1+hh1) + q12*row[12];
}

#define M25 0x01FFFFFFu

// ---------------- pre-LN transformer block, packed activations ----------------
__device__ __forceinline__ void xblock(float (&x)[26], int lane, float* __restrict__ sm,
                                       float* __restrict__ SCR)
{
  // LN1 -> packed h2
  u64 h2[13];
  {
    float s = 0.f;
#pragma unroll
    for (int e = 0; e < 26; e++) s += x[e];
    float m = s * (1.f/26.f);
    float vv = 0.f;
#pragma unroll
    for (int e = 0; e < 26; e++){ float d = x[e]-m; vv += d*d; }
    float r = rsqrtf(vv*(1.f/26.f) + 1e-6f);
#pragma unroll
    for (int e = 0; e < 13; e++){
      float lo = (x[2*e]-m)*r*sm[OFF_LN1G+2*e]   + sm[OFF_LN1B+2*e];
      float hi = (x[2*e+1]-m)*r*sm[OFF_LN1G+2*e+1] + sm[OFF_LN1B+2*e+1];
      h2[e] = pack2(lo, hi);
    }
  }

  float ao[26];
#pragma unroll
  for (int head = 0; head < 2; head++){
    float qd[13];
#pragma unroll
    for (int d = 0; d < 13; d++)
      qd[d] = sm[OFF_BQKV + head*13 + d]
            + dot26p(sm + OFF_WQKV + (head*13+d)*28, h2);
    u64 qp[6];
#pragma unroll
    for (int i = 0; i < 6; i++) qp[i] = pack2(qd[2*i], qd[2*i+1]);
    float q12 = qd[12];

#pragma unroll 2
    for (int d = 0; d < 13; d++)
      SCR[lane*28 + d] = sm[OFF_BQKV + 26 + head*13 + d]
                       + dot26p(sm + OFF_WQKV + (26+head*13+d)*28, h2);
    __syncwarp(M25);

    float p[25];
    float mx = -1e30f;
#pragma unroll
    for (int j = 0; j < 25; j++){
      float s = dot13p(SCR + j*28, qp, q12) * 0.2773500981126146f;
      p[j] = s; mx = fmaxf(mx, s);
    }
    float se = 0.f;
#pragma unroll
    for (int j = 0; j < 25; j++){ float e2 = __expf(p[j]-mx); p[j] = e2; se += e2; }
    float inv = 1.f/se;
#pragma unroll
    for (int j = 0; j < 25; j++) p[j] *= inv;
    __syncwarp(M25);

#pragma unroll 2
    for (int d = 0; d < 13; d++)
      SCR[lane*28 + d] = sm[OFF_BQKV + 52 + head*13 + d]
                       + dot26p(sm + OFF_WQKV + (52+head*13+d)*28, h2);
    __syncwarp(M25);

    u64 oa[6];
#pragma unroll
    for (int i = 0; i < 6; i++) oa[i] = 0ull;
    float o12 = 0.f;
#pragma unroll
    for (int j = 0; j < 25; j++){
      const float* vr = SCR + j*28;
      const ulonglong2* v2 = (const ulonglong2*)vr;
      ulonglong2 a = v2[0], b = v2[1], c = v2[2];
      float pj = p[j];
      u64 pj2 = pack2(pj, pj);
      oa[0] = fma2(a.x, pj2, oa[0]); oa[1] = fma2(a.y, pj2, oa[1]);
      oa[2] = fma2(b.x, pj2, oa[2]); oa[3] = fma2(b.y, pj2, oa[3]);
      oa[4] = fma2(c.x, pj2, oa[4]); oa[5] = fma2(c.y, pj2, oa[5]);
      o12 += pj*vr[12];
    }
#pragma unroll
    for (int i = 0; i < 6; i++)
      unpack2(oa[i], ao[head*13 + 2*i], ao[head*13 + 2*i + 1]);
    ao[head*13 + 12] = o12;
    __syncwarp(M25);
  }

  // attn proj + residual
  {
    u64 ao2[13];
#pragma unroll
    for (int e = 0; e < 13; e++) ao2[e] = pack2(ao[2*e], ao[2*e+1]);
#pragma unroll
    for (int e = 0; e < 26; e++)
      x[e] += sm[OFF_BATT+e] + dot26p(sm + OFF_WATT + e*28, ao2);
  }

  // LN2 -> packed h2
  {
    float s = 0.f;
#pragma unroll
    for (int e = 0; e < 26; e++) s += x[e];
    float m = s * (1.f/26.f);
    float vv = 0.f;
#pragma unroll
    for (int e = 0; e < 26; e++){ float d = x[e]-m; vv += d*d; }
    float r = rsqrtf(vv*(1.f/26.f) + 1e-6f);
#pragma unroll
    for (int e = 0; e < 13; e++){
      float lo = (x[2*e]-m)*r*sm[OFF_LN2G+2*e]   + sm[OFF_LN2B+2*e];
      float hi = (x[2*e+1]-m)*r*sm[OFF_LN2G+2*e+1] + sm[OFF_LN2B+2*e+1];
      h2[e] = pack2(lo, hi);
    }
  }

  // fused FFN
  {
    u64 xa[13];
#pragma unroll
    for (int e = 0; e < 13; e++)
      xa[e] = pack2(x[2*e] + sm[OFF_BFC2+2*e], x[2*e+1] + sm[OFF_BFC2+2*e+1]);
#pragma unroll 2
    for (int n = 0; n < 104; n++){
      float g = sm[OFF_BFC1+n] + dot26p(sm + OFF_WFC1 + n*28, h2);
      g = 0.5f*g*(1.f + erff(g*0.70710678118654752f));
      u64 g2 = pack2(g, g);
      const float* w2 = sm + OFF_WFC2T + n*28;
      const ulonglong2* w4 = (const ulonglong2*)w2;
      ulonglong2 a = w4[0], b = w4[1], c = w4[2];
      xa[0] = fma2(a.x, g2, xa[0]); xa[1] = fma2(a.y, g2, xa[1]);
      xa[2] = fma2(b.x, g2, xa[2]); xa[3] = fma2(b.y, g2, xa[3]);
      xa[4] = fma2(c.x, g2, xa[4]); xa[5] = fma2(c.y, g2, xa[5]);
      ulonglong2 d4 = w4[3], e4 = w4[4], f4 = w4[5];
      xa[6]  = fma2(d4.x, g2, xa[6]);  xa[7]  = fma2(d4.y, g2, xa[7]);
      xa[8]  = fma2(e4.x, g2, xa[8]);  xa[9]  = fma2(e4.y, g2, xa[9]);
      xa[10] = fma2(f4.x, g2, xa[10]); xa[11] = fma2(f4.y, g2, xa[11]);
      xa[12] = fma2(((const u64*)w2)[12], g2, xa[12]);
    }
#pragma unroll
    for (int e = 0; e < 13; e++) unpack2(xa[e], x[2*e], x[2*e+1]);
  }
}

// ---------------- main fused kernel: CTA = QPB queries x 5 ways, warp per pair ------
__global__ __launch_bounds__(BLK, 1) void pair_kernel(
    const float* __restrict__ pos_x, const float* __restrict__ pos_y,
    const float* __restrict__ ln1_g, const float* __restrict__ ln1_b,
    const float* __restrict__ qkv_w, const float* __restrict__ qkv_b,
    const float* __restrict__ attn_w, const float* __restrict__ attn_b,
    const float* __restrict__ ln2_g, const float* __restrict__ ln2_b,
    const float* __restrict__ fc1_w, const float* __restrict__ fc1_b,
    const float* __restrict__ fc2_w, const float* __restrict__ fc2_b,
    const float* __restrict__ dec_w, const float* __restrict__ dec_b,
    float* __restrict__ out)
{
  extern __shared__ float sm[];
  const int q0 = blockIdx.x * QPB;
  const int tid = threadIdx.x;

  // ---- stage weights (shared by all 20 warps) ----
  for (int idx = tid; idx < 78*26; idx += BLK)  sm[OFF_WQKV + (idx/26)*28 + idx%26] = qkv_w[idx];
  for (int idx = tid; idx < 26*26; idx += BLK)  sm[OFF_WATT + (idx/26)*28 + idx%26] = attn_w[idx];
  for (int idx = tid; idx < 104*26; idx += BLK) sm[OFF_WFC1 + (idx/26)*28 + idx%26] = fc1_w[idx];
  for (int idx = tid; idx < 26*104; idx += BLK){ int e = idx/104, f = idx%104;
                                                 sm[OFF_WFC2T + f*28 + e] = fc2_w[idx]; }
  for (int idx = tid; idx < 25*26; idx += BLK)  sm[OFF_WDEC + (idx/26)*28 + idx%26] = dec_w[idx];
  if (tid < 78)  sm[OFF_BQKV+tid] = qkv_b[tid];
  if (tid < 104) sm[OFF_BFC1+tid] = fc1_b[tid];
  if (tid < 26){
    sm[OFF_BATT+tid] = attn_b[tid]; sm[OFF_BFC2+tid] = fc2_b[tid];
    sm[OFF_LN1G+tid] = ln1_g[tid];  sm[OFF_LN1B+tid] = ln1_b[tid];
    sm[OFF_LN2G+tid] = ln2_g[tid];  sm[OFF_LN2B+tid] = ln2_b[tid];
  }
  if (tid >= 32 && tid < 57) sm[OFF_BDEC + tid-32] = dec_b[tid-32];
  for (int idx = tid; idx < 650; idx += BLK){
    int p = idx/26, e = idx%26, px = p/5, py = p%5;
    sm[OFF_POS + p*27 + e] = (e < 13) ? pos_x[py*13 + e] : pos_y[px*13 + (e-13)];
  }
  for (int idx = tid; idx < 5*1600; idx += BLK){
    int ww = idx/1600, r = idx%1600, c = r/25, i = r%25;
    sm[OFF_SN + ww*1792 + c*28 + i] = g_sn[idx];
  }
  for (int idx = tid; idx < QPB*1600; idx += BLK){
    int sq = idx/1600, r = idx%1600, c = r/25, j = r%25;
    sm[OFF_QN + sq*1792 + c*28 + j] = g_qn[(q0+sq)*1600 + r];
  }
  for (int idx = tid; idx < 125; idx += BLK){ sm[OFF_RS+idx] = g_rs[idx]; sm[OFF_SP+idx] = g_sp[idx]; }
  for (int idx = tid; idx < QPB*25; idx += BLK){
    int sq = idx/25, j = idx%25;
    sm[OFF_RQ + sq*25 + j] = g_rq[(q0+sq)*25 + j];
    sm[OFF_TP + sq*25 + j] = g_tp[(q0+sq)*25 + j];
  }
  __syncthreads();

  const int wid  = tid >> 5;            // 0..19
  const int subq = wid / WAYv;          // query within CTA
  const int w    = wid - subq*WAYv;     // way
  const int lane = tid & 31;
  const int q    = q0 + subq;

  float* SNw   = sm + OFF_SN   + w*1792;
  float* QNq   = sm + OFF_QN   + subq*1792;
  float* SCR   = sm + OFF_SCR  + wid*700;
  float* CORR  = sm + OFF_CORR + wid*725;
  float* ATTSw = sm + OFF_ATTS + wid*32;
  float* ATTQw = sm + OFF_ATTQ + wid*32;
  const float* RQq = sm + OFF_RQ + subq*25;
  const float* TPq = sm + OFF_TP + subq*25;

  if (lane < 25){
    // ---- corr (packed accumulators) ----
    u64 a2[12];
#pragma unroll
    for (int i = 0; i < 12; i++) a2[i] = 0ull;
    float a24 = 0.f;
    for (int c = 0; c < 64; c++){
      float qc = QNq[c*28 + lane];
      u64 qc2 = pack2(qc, qc);
      const float* srow = SNw + c*28;
      const ulonglong2* s2 = (const ulonglong2*)srow;
      ulonglong2 v0=s2[0], v1=s2[1], v2=s2[2], v3=s2[3], v4=s2[4], v5=s2[5];
      a2[0] = fma2(v0.x,qc2,a2[0]); a2[1] = fma2(v0.y,qc2,a2[1]);
      a2[2] = fma2(v1.x,qc2,a2[2]); a2[3] = fma2(v1.y,qc2,a2[3]);
      a2[4] = fma2(v2.x,qc2,a2[4]); a2[5] = fma2(v2.y,qc2,a2[5]);
      a2[6] = fma2(v3.x,qc2,a2[6]); a2[7] = fma2(v3.y,qc2,a2[7]);
      a2[8] = fma2(v4.x,qc2,a2[8]); a2[9] = fma2(v4.y,qc2,a2[9]);
      a2[10]= fma2(v5.x,qc2,a2[10]);a2[11]= fma2(v5.y,qc2,a2[11]);
      a24 += srow[24]*qc;
    }
    float rq = RQq[lane];
    float acc[25];
#pragma unroll
    for (int i = 0; i < 12; i++) unpack2(a2[i], acc[2*i], acc[2*i+1]);
    acc[24] = a24;
#pragma unroll
    for (int i = 0; i < 25; i++)
      CORR[i*29 + lane] = acc[i] * sm[OFF_RS + w*25 + i] * rq;
    __syncwarp(M25);

    // ---- x1 ----
    float x[26];
#pragma unroll
    for (int e = 0; e < 25; e++) x[e] = CORR[e*29 + lane];
    x[25] = TPq[lane];
#pragma unroll
    for (int e = 0; e < 26; e++) x[e] += sm[OFF_POS + lane*27 + e];

    xblock(x, lane, sm, SCR);

    // dec1 -> SCR
    {
      u64 x2[13];
#pragma unroll
      for (int e = 0; e < 13; e++) x2[e] = pack2(x[2*e], x[2*e+1]);
#pragma unroll 2
      for (int o = 0; o < 25; o++)
        SCR[lane*28 + o] = sm[OFF_BDEC+o] + dot26p(sm + OFF_WDEC + o*28, x2);
    }
    __syncwarp(M25);

    // ---- x2 ----
#pragma unroll
    for (int e = 0; e < 25; e++) x[e] = SCR[e*28 + lane] + CORR[lane*29 + e];
    x[25] = sm[OFF_SP + w*25 + lane];
#pragma unroll
    for (int e = 0; e < 26; e++) x[e] += sm[OFF_POS + lane*27 + e];
    __syncwarp(M25);

    xblock(x, lane, sm, SCR);

    // dec2 + refined row
    float y[25];
    {
      u64 x2[13];
#pragma unroll
      for (int e = 0; e < 13; e++) x2[e] = pack2(x[2*e], x[2*e+1]);
#pragma unroll 2
      for (int o = 0; o < 25; o++)
        y[o] = sm[OFF_BDEC+o] + dot26p(sm + OFF_WDEC + o*28, x2) + CORR[lane*29 + o];
    }
#pragma unroll
    for (int o = 0; o < 25; o++) CORR[lane*29 + o] = y[o];
    __syncwarp(M25);

    // ---- attn_q ----
    {
      float s = 0.f;
#pragma unroll
      for (int j = 0; j < 25; j++) s += y[j];
      float m = s*(1.f/25.f);
      float vv = 0.f;
#pragma unroll
      for (int j = 0; j < 25; j++){ float d = y[j]-m; vv += d*d; }
      float inv = 0.2f * rsqrtf(vv*(1.f/24.f) + 1e-5f);
      float mx = -1e30f;
#pragma unroll
      for (int j = 0; j < 25; j++){ float z = (y[j]-m)*inv; y[j] = z; mx = fmaxf(mx, z); }
      float se = 0.f;
#pragma unroll
      for (int j = 0; j < 25; j++){ float e2 = __expf(y[j]-mx); y[j] = e2; se += e2; }
      float is = 1.f/se;
#pragma unroll
      for (int j = 0; j < 25; j++) SCR[lane*28 + j] = y[j]*is;
    }
    __syncwarp(M25);
    {
      float s = 0.f;
#pragma unroll
      for (int i = 0; i < 25; i++) s += SCR[i*28 + lane];
      ATTQw[lane] = s;
    }
    __syncwarp(M25);

    // ---- attn_s ----
    {
      float col[25];
#pragma unroll
      for (int i = 0; i < 25; i++) col[i] = CORR[i*29 + lane];
      float s = 0.f;
#pragma unroll
      for (int i = 0; i < 25; i++) s += col[i];
      float m = s*(1.f/25.f);
      float vv = 0.f;
#pragma unroll
      for (int i = 0; i < 25; i++){ float d = col[i]-m; vv += d*d; }
      float inv = 0.2f * rsqrtf(vv*(1.f/24.f) + 1e-5f);
      float mx = -1e30f;
#pragma unroll
      for (int i = 0; i < 25; i++){ float z = (col[i]-m)*inv; col[i] = z; mx = fmaxf(mx, z); }
      float se = 0.f;
#pragma unroll
      for (int i = 0; i < 25; i++){ float e2 = __expf(col[i]-mx); col[i] = e2; se += e2; }
      float is = 1.f/se;
#pragma unroll
      for (int i = 0; i < 25; i++) SCR[i*28 + lane] = col[i]*is;
    }
    __syncwarp(M25);
    {
      float s = 0.f;
#pragma unroll
      for (int j = 0; j < 25; j++) s += SCR[lane*28 + j];
      ATTSw[lane] = s;
    }
  }
  __syncwarp();

  // ---- pooling + cosine sim ----
  {
    int c0 = lane, c1 = lane + 32;
    float sp0=0.f, sp1=0.f, qp0=0.f, qp1=0.f;
#pragma unroll
    for (int t = 0; t < 25; t++){
      float as_ = ATTSw[t], aq_ = ATTQw[t];
      sp0 += as_ * SNw[c0*28 + t];
      sp1 += as_ * SNw[c1*28 + t];
      qp0 += aq_ * QNq[c0*28 + t];
      qp1 += aq_ * QNq[c1*28 + t];
    }
    sp0 *= 0.04f; sp1 *= 0.04f; qp0 *= 0.04f; qp1 *= 0.04f;
    float dd = sp0*qp0 + sp1*qp1;
    float na = sp0*sp0 + sp1*sp1;
    float nb = qp0*qp0 + qp1*qp1;
#pragma unroll
    for (int off = 16; off; off >>= 1){
      dd += __shfl_xor_sync(0xFFFFFFFFu, dd, off);
      na += __shfl_xor_sync(0xFFFFFFFFu, na, off);
      nb += __shfl_xor_sync(0xFFFFFFFFu, nb, off);
    }
    if (lane == 0){
      float n1 = fmaxf(sqrtf(na), 1e-8f);
      float n2 = fmaxf(sqrtf(nb), 1e-8f);
      out[q*WAYv + w] = dd / (n1*n2) * 5.0f;
    }
  }
}

// ---------------- launch ----------------
extern "C" void kernel_launch(void* const* d_in, const int* in_sizes, int n_in,
                              void* d_out, int out_size)
{
  const float* spt    = (const float*)d_in[0];
  const float* qry    = (const float*)d_in[1];
  const float* proj_w = (const float*)d_in[2];
  const float* proj_b = (const float*)d_in[3];
  const float* pos_x  = (const float*)d_in[4];
  const float* pos_y  = (const float*)d_in[5];
  const float* ln1_g  = (const float*)d_in[6];
  const float* ln1_b  = (const float*)d_in[7];
  const float* qkv_w  = (const float*)d_in[8];
  const float* qkv_b  = (const float*)d_in[9];
  const float* attn_w = (const float*)d_in[10];
  const float* attn_b = (const float*)d_in[11];
  const float* ln2_g  = (const float*)d_in[12];
  const float* ln2_b  = (const float*)d_in[13];
  const float* fc1_w  = (const float*)d_in[14];
  const float* fc1_b  = (const float*)d_in[15];
  const float* fc2_w  = (const float*)d_in[16];
  const float* fc2_b  = (const float*)d_in[17];
  const float* dec_w  = (const float*)d_in[18];
  const float* dec_b  = (const float*)d_in[19];
  float* out = (float*)d_out;

  float *qn, *rq, *tp, *sn, *rs, *sp;
  cudaGetSymbolAddress((void**)&qn, g_qn);
  cudaGetSymbolAddress((void**)&rq, g_rq);
  cudaGetSymbolAddress((void**)&tp, g_tp);
  cudaGetSymbolAddress((void**)&sn, g_sn);
  cudaGetSymbolAddress((void**)&rs, g_rs);
  cudaGetSymbolAddress((void**)&sp, g_sp);

  prep_kernel<<<WAYv, 32>>>(spt, proj_w, proj_b, sn, rs, sp);
  prep_kernel<<<NQv, 32>>>(qry, proj_w, proj_b, qn, rq, tp);

  size_t shmem = SMEM_FLOATS * sizeof(float);
  static int configured = -1;
  if (configured < 0){
    cudaFuncSetAttribute(pair_kernel, cudaFuncAttributeMaxDynamicSharedMemorySize, (int)shmem);
    configured = 1;
  }
  pair_kernel<<<NQv/QPB, BLK, shmem>>>(
      pos_x, pos_y, ln1_g, ln1_b, qkv_w, qkv_b, attn_w, attn_b,
      ln2_g, ln2_b, fc1_w, fc1_b, fc2_w, fc2_b, dec_w, dec_b, out);
}

// round 12
// speedup vs baseline: 3.2519x; 1.0428x over previous
#include <cuda_runtime.h>
#include <math.h>

#define NQv 4096
#define WAYv 5
#define Cv 64
#define Tv 25
#define QPB 4                 // queries per CTA (4096 % 4 == 0)
#define BLK (QPB*WAYv*32)     // 640 threads = 20 warps

typedef unsigned long long u64;

// ---------------- f32x2 packed helpers ----------------
__device__ __forceinline__ u64 pack2(float lo, float hi){
  u64 r; asm("mov.b64 %0, {%1, %2};" : "=l"(r) : "f"(lo), "f"(hi)); return r;
}
__device__ __forceinline__ void unpack2(u64 v, float& lo, float& hi){
  asm("mov.b64 {%0, %1}, %2;" : "=f"(lo), "=f"(hi) : "l"(v));
}
__device__ __forceinline__ u64 fma2(u64 a, u64 b, u64 c){
  u64 d; asm("fma.rn.f32x2 %0, %1, %2, %3;" : "=l"(d) : "l"(a), "l"(b), "l"(c)); return d;
}
__device__ __forceinline__ u64 mul2(u64 a, u64 b){
  u64 d; asm("mul.rn.f32x2 %0, %1, %2;" : "=l"(d) : "l"(a), "l"(b)); return d;
}
__device__ __forceinline__ float tanh_fast(float a){
  float t; asm("tanh.approx.f32 %0, %1;" : "=f"(t) : "f"(a)); return t;
}

// ---------------- global scratch (pair-independent precompute) ----------------
__device__ float g_qn[NQv*Cv*Tv];
__device__ float g_rq[NQv*Tv];
__device__ float g_tp[NQv*Tv];
__device__ float g_sn[WAYv*Cv*Tv];
__device__ float g_rs[WAYv*Tv];
__device__ float g_sp[WAYv*Tv];

// ---------------- shared layout (floats), 16B-aligned vector regions first ----------
enum {
  OFF_WQKV = 0,                       // 78 x 28
  OFF_WATT = OFF_WQKV + 78*28,        // 26 x 28
  OFF_WFC1 = OFF_WATT + 26*28,        // 104 x 28
  OFF_WFC2T= OFF_WFC1 + 104*28,       // 104 x 28 (fc2 transposed)
  OFF_WDEC = OFF_WFC2T + 104*28,      // 25 x 28
  OFF_LNGB = OFF_WDEC + 25*28,        // 2 x 56: interleaved (g,g,b,b) quads, LN1 then LN2
  OFF_SN   = OFF_LNGB + 112,          // 5 x 64 x 28      (per way)
  OFF_QN   = OFF_SN + 5*64*28,        // QPB x 64 x 28    (per query)
  OFF_SCR  = OFF_QN + QPB*64*28,      // 20 x 25 x 28     (per warp)
  OFF_CORR = OFF_SCR + QPB*5*700,     // 20 x 25 x 29     (per warp)
  OFF_BQKV = OFF_CORR + QPB*5*725,
  OFF_BATT = OFF_BQKV + 78,
  OFF_BFC1 = OFF_BATT + 26,
  OFF_BFC2 = OFF_BFC1 + 104,
  OFF_BDEC = OFF_BFC2 + 26,
  OFF_POS  = OFF_BDEC + 25,           // 25 x 27
  OFF_RS   = OFF_POS + 25*27,         // 5 x 25
  OFF_SP   = OFF_RS + 125,            // 5 x 25
  OFF_RQ   = OFF_SP + 125,            // QPB x 25
  OFF_TP   = OFF_RQ + QPB*25,         // QPB x 25
  OFF_ATTS = OFF_TP + QPB*25,         // 20 x 32
  OFF_ATTQ = OFF_ATTS + QPB*5*32,     // 20 x 32
  SMEM_FLOATS = OFF_ATTQ + QPB*5*32
};

// ---------------- prep ----------------
__global__ void prep_kernel(const float* __restrict__ in,
                            const float* __restrict__ pw,
                            const float* __restrict__ pb,
                            float* __restrict__ on,
                            float* __restrict__ orr,
                            float* __restrict__ op)
{
  int img = blockIdx.x;
  int t = threadIdx.x;
  if (t >= Tv) return;
  const float* base = in + img*Cv*Tv;
  float v[Cv];
  float s = 0.f;
#pragma unroll
  for (int c = 0; c < Cv; c++){ v[c] = base[c*Tv + t]; s += v[c]; }
  float m = s * (1.f/64.f);
  float ss0=0.f, ss1=0.f, pj0=0.f, pj1=0.f;
#pragma unroll
  for (int c = 0; c < Cv; c += 2){
    float d0 = v[c]-m, d1 = v[c+1]-m;
    on[img*Cv*Tv + c*Tv + t]     = d0;
    on[img*Cv*Tv + (c+1)*Tv + t] = d1;
    ss0 += d0*d0; ss1 += d1*d1;
    pj0 += d0*pw[c]; pj1 += d1*pw[c+1];
  }
  orr[img*Tv + t] = rsqrtf(ss0+ss1 + 1e-6f);
  op[img*Tv + t]  = pj0+pj1 + pb[0];
}

// ---------------- packed dot helpers ----------------
__device__ __forceinline__ float dot26p(const float* __restrict__ row, const u64 (&h2)[13]){
  const ulonglong2* r2 = (const ulonglong2*)row;
  u64 a0 = 0ull, a1 = 0ull;
  ulonglong2 v0 = r2[0], v1 = r2[1], v2 = r2[2];
  a0 = fma2(v0.x, h2[0], a0);  a1 = fma2(v0.y, h2[1], a1);
  a0 = fma2(v1.x, h2[2], a0);  a1 = fma2(v1.y, h2[3], a1);
  a0 = fma2(v2.x, h2[4], a0);  a1 = fma2(v2.y, h2[5], a1);
  ulonglong2 v3 = r2[3], v4 = r2[4], v5 = r2[5];
  a0 = fma2(v3.x, h2[6], a0);  a1 = fma2(v3.y, h2[7], a1);
  a0 = fma2(v4.x, h2[8], a0);  a1 = fma2(v4.y, h2[9], a1);
  a0 = fma2(v5.x, h2[10], a0); a1 = fma2(v5.y, h2[11], a1);
  a0 = fma2(((const u64*)row)[12], h2[12], a0);
  float l0,hh0,l1,hh1;
  unpack2(a0,l0,hh0); unpack2(a1,l1,hh1);
  return (l0+hh0)+(l1+hh1);
}

__device__ __forceinline__ float dot13p(const float* __restrict__ row,
                                        const u64 (&qp)[6], float q12){
  const ulonglong2* r2 = (const ulonglong2*)row;
  ulonglong2 v0 = r2[0], v1 = r2[1], v2 = r2[2];
  u64 a0 = 0ull, a1 = 0ull;
  a0 = fma2(v0.x, qp[0], a0); a1 = fma2(v0.y, qp[1], a1);
  a0 = fma2(v1.x, qp[2], a0); a1 = fma2(v1.y, qp[3], a1);
  a0 = fma2(v2.x, qp[4], a0); a1 = fma2(v2.y, qp[5], a1);
  float l0,hh0,l1,hh1;
  unpack2(a0,l0,hh0); unpack2(a1,l1,hh1);
  return (l0+hh0)+(l1+hh1) + q12*row[12];
}

#define M25 0x01FFFFFFu

// ---------------- layernorm -> packed h2, vectorized gamma/beta ----------------
__device__ __forceinline__ void ln_packed(const float (&x)[26], const float* __restrict__ gb,
                                          u64 (&h2)[13])
{
  float s = 0.f;
#pragma unroll
  for (int e = 0; e < 26; e++) s += x[e];
  float m = s * (1.f/26.f);
  float vv = 0.f;
#pragma unroll
  for (int e = 0; e < 26; e++){ float d = x[e]-m; vv += d*d; }
  float r = rsqrtf(vv*(1.f/26.f) + 1e-6f);
  u64 r2 = pack2(r, r);
  const ulonglong2* gb2 = (const ulonglong2*)gb;
#pragma unroll
  for (int e = 0; e < 13; e++){
    ulonglong2 v = gb2[e];              // v.x = (g_lo,g_hi), v.y = (b_lo,b_hi)
    u64 s2 = pack2(x[2*e]-m, x[2*e+1]-m);
    h2[e] = fma2(mul2(s2, r2), v.x, v.y);
  }
}

// ---------------- pre-LN transformer block, packed activations ----------------
__device__ __forceinline__ void xblock(float (&x)[26], int lane, float* __restrict__ sm,
                                       float* __restrict__ SCR)
{
  u64 h2[13];
  ln_packed(x, sm + OFF_LNGB, h2);

  float ao[26];
#pragma unroll
  for (int head = 0; head < 2; head++){
    float qd[13];
#pragma unroll
    for (int d = 0; d < 13; d++)
      qd[d] = sm[OFF_BQKV + head*13 + d]
            + dot26p(sm + OFF_WQKV + (head*13+d)*28, h2);
    u64 qp[6];
#pragma unroll
    for (int i = 0; i < 6; i++) qp[i] = pack2(qd[2*i], qd[2*i+1]);
    float q12 = qd[12];

#pragma unroll 2
    for (int d = 0; d < 13; d++)
      SCR[lane*28 + d] = sm[OFF_BQKV + 26 + head*13 + d]
                       + dot26p(sm + OFF_WQKV + (26+head*13+d)*28, h2);
    __syncwarp(M25);

    // scores + softmax; |score| << 1 guaranteed (0.02-scale weights on LN output),
    // so no max-subtraction needed; 1/sum folded into AV epilogue.
    float p[25];
    float se = 0.f;
#pragma unroll
    for (int j = 0; j < 25; j++){
      float s = dot13p(SCR + j*28, qp, q12) * 0.2773500981126146f;
      float e2 = __expf(s);
      p[j] = e2; se += e2;
    }
    float inv = __fdividef(1.f, se);
    __syncwarp(M25);

#pragma unroll 2
    for (int d = 0; d < 13; d++)
      SCR[lane*28 + d] = sm[OFF_BQKV + 52 + head*13 + d]
                       + dot26p(sm + OFF_WQKV + (52+head*13+d)*28, h2);
    __syncwarp(M25);

    u64 oa[6];
#pragma unroll
    for (int i = 0; i < 6; i++) oa[i] = 0ull;
    float o12 = 0.f;
#pragma unroll
    for (int j = 0; j < 25; j++){
      const float* vr = SCR + j*28;
      const ulonglong2* v2 = (const ulonglong2*)vr;
      ulonglong2 a = v2[0], b = v2[1], c = v2[2];
      float pj = p[j];
      u64 pj2 = pack2(pj, pj);
      oa[0] = fma2(a.x, pj2, oa[0]); oa[1] = fma2(a.y, pj2, oa[1]);
      oa[2] = fma2(b.x, pj2, oa[2]); oa[3] = fma2(b.y, pj2, oa[3]);
      oa[4] = fma2(c.x, pj2, oa[4]); oa[5] = fma2(c.y, pj2, oa[5]);
      o12 += pj*vr[12];
    }
    u64 inv2 = pack2(inv, inv);
#pragma unroll
    for (int i = 0; i < 6; i++){
      oa[i] = mul2(oa[i], inv2);
      unpack2(oa[i], ao[head*13 + 2*i], ao[head*13 + 2*i + 1]);
    }
    ao[head*13 + 12] = o12 * inv;
    __syncwarp(M25);
  }

  // attn proj + residual
  {
    u64 ao2[13];
#pragma unroll
    for (int e = 0; e < 13; e++) ao2[e] = pack2(ao[2*e], ao[2*e+1]);
#pragma unroll
    for (int e = 0; e < 26; e++)
      x[e] += sm[OFF_BATT+e] + dot26p(sm + OFF_WATT + e*28, ao2);
  }

  u64 g2ln[13];
  ln_packed(x, sm + OFF_LNGB + 56, g2ln);

  // fused FFN (tanh-GELU)
  {
    u64 xa[13];
#pragma unroll
    for (int e = 0; e < 13; e++)
      xa[e] = pack2(x[2*e] + sm[OFF_BFC2+2*e], x[2*e+1] + sm[OFF_BFC2+2*e+1]);
#pragma unroll 2
    for (int n = 0; n < 104; n++){
      float g = sm[OFF_BFC1+n] + dot26p(sm + OFF_WFC1 + n*28, g2ln);
      // gelu(x) ~= 0.5x(1+tanh(0.79788456(x + 0.044715x^3)))
      float gg = g*g;
      float arg = g * fmaf(gg, 0.0356774081f, 0.7978845608f);
      float th = tanh_fast(arg);
      float hg = 0.5f*g;
      g = fmaf(hg, th, hg);
      u64 g2 = pack2(g, g);
      const float* w2 = sm + OFF_WFC2T + n*28;
      const ulonglong2* w4 = (const ulonglong2*)w2;
      ulonglong2 a = w4[0], b = w4[1], c = w4[2];
      xa[0] = fma2(a.x, g2, xa[0]); xa[1] = fma2(a.y, g2, xa[1]);
      xa[2] = fma2(b.x, g2, xa[2]); xa[3] = fma2(b.y, g2, xa[3]);
      xa[4] = fma2(c.x, g2, xa[4]); xa[5] = fma2(c.y, g2, xa[5]);
      ulonglong2 d4 = w4[3], e4 = w4[4], f4 = w4[5];
      xa[6]  = fma2(d4.x, g2, xa[6]);  xa[7]  = fma2(d4.y, g2, xa[7]);
      xa[8]  = fma2(e4.x, g2, xa[8]);  xa[9]  = fma2(e4.y, g2, xa[9]);
      xa[10] = fma2(f4.x, g2, xa[10]); xa[11] = fma2(f4.y, g2, xa[11]);
      xa[12] = fma2(((const u64*)w2)[12], g2, xa[12]);
    }
#pragma unroll
    for (int e = 0; e < 13; e++) unpack2(xa[e], x[2*e], x[2*e+1]);
  }
}

// ---------------- main fused kernel: CTA = QPB queries x 5 ways, warp per pair ------
__global__ __launch_bounds__(BLK, 1) void pair_kernel(
    const float* __restrict__ pos_x, const float* __restrict__ pos_y,
    const float* __restrict__ ln1_g, const float* __restrict__ ln1_b,
    const float* __restrict__ qkv_w, const float* __restrict__ qkv_b,
    const float* __restrict__ attn_w, const float* __restrict__ attn_b,
    const float* __restrict__ ln2_g, const float* __restrict__ ln2_b,
    const float* __restrict__ fc1_w, const float* __restrict__ fc1_b,
    const float* __restrict__ fc2_w, const float* __restrict__ fc2_b,
    const float* __restrict__ dec_w, const float* __restrict__ dec_b,
    float* __restrict__ out)
{
  extern __shared__ float sm[];
  const int q0 = blockIdx.x * QPB;
  const int tid = threadIdx.x;

  // ---- stage weights (shared by all 20 warps) ----
  for (int idx = tid; idx < 78*26; idx += BLK)  sm[OFF_WQKV + (idx/26)*28 + idx%26] = qkv_w[idx];
  for (int idx = tid; idx < 26*26; idx += BLK)  sm[OFF_WATT + (idx/26)*28 + idx%26] = attn_w[idx];
  for (int idx = tid; idx < 104*26; idx += BLK) sm[OFF_WFC1 + (idx/26)*28 + idx%26] = fc1_w[idx];
  for (int idx = tid; idx < 26*104; idx += BLK){ int e = idx/104, f = idx%104;
                                                 sm[OFF_WFC2T + f*28 + e] = fc2_w[idx]; }
  for (int idx = tid; idx < 25*26; idx += BLK)  sm[OFF_WDEC + (idx/26)*28 + idx%26] = dec_w[idx];
  // LN gamma/beta interleaved (g,g,b,b) quads for vector loads
  if (tid < 52){
    int gi = tid >> 2, r = tid & 3;
    sm[OFF_LNGB + tid]      = (r < 2) ? ln1_g[2*gi + r] : ln1_b[2*gi + r - 2];
    sm[OFF_LNGB + 56 + tid] = (r < 2) ? ln2_g[2*gi + r] : ln2_b[2*gi + r - 2];
  }
  if (tid < 78)  sm[OFF_BQKV+tid] = qkv_b[tid];
  if (tid < 104) sm[OFF_BFC1+tid] = fc1_b[tid];
  if (tid < 26){ sm[OFF_BATT+tid] = attn_b[tid]; sm[OFF_BFC2+tid] = fc2_b[tid]; }
  if (tid >= 32 && tid < 57) sm[OFF_BDEC + tid-32] = dec_b[tid-32];
  for (int idx = tid; idx < 650; idx += BLK){
    int p = idx/26, e = idx%26, px = p/5, py = p%5;
    sm[OFF_POS + p*27 + e] = (e < 13) ? pos_x[py*13 + e] : pos_y[px*13 + (e-13)];
  }
  for (int idx = tid; idx < 5*1600; idx += BLK){
    int ww = idx/1600, r = idx%1600, c = r/25, i = r%25;
    sm[OFF_SN + ww*1792 + c*28 + i] = g_sn[idx];
  }
  for (int idx = tid; idx < QPB*1600; idx += BLK){
    int sq = idx/1600, r = idx%1600, c = r/25, j = r%25;
    sm[OFF_QN + sq*1792 + c*28 + j] = g_qn[(q0+sq)*1600 + r];
  }
  for (int idx = tid; idx < 125; idx += BLK){ sm[OFF_RS+idx] = g_rs[idx]; sm[OFF_SP+idx] = g_sp[idx]; }
  for (int idx = tid; idx < QPB*25; idx += BLK){
    int sq = idx/25, j = idx%25;
    sm[OFF_RQ + sq*25 + j] = g_rq[(q0+sq)*25 + j];
    sm[OFF_TP + sq*25 + j] = g_tp[(q0+sq)*25 + j];
  }
  __syncthreads();

  const int wid  = tid >> 5;            // 0..19
  const int subq = wid / WAYv;          // query within CTA
  const int w    = wid - subq*WAYv;     // way
  const int lane = tid & 31;
  const int q    = q0 + subq;

  float* SNw   = sm + OFF_SN   + w*1792;
  float* QNq   = sm + OFF_QN   + subq*1792;
  float* SCR   = sm + OFF_SCR  + wid*700;
  float* CORR  = sm + OFF_CORR + wid*725;
  float* ATTSw = sm + OFF_ATTS + wid*32;
  float* ATTQw = sm + OFF_ATTQ + wid*32;
  const float* RQq = sm + OFF_RQ + subq*25;
  const float* TPq = sm + OFF_TP + subq*25;

  if (lane < 25){
    // ---- corr (packed accumulators) ----
    u64 a2[12];
#pragma unroll
    for (int i = 0; i < 12; i++) a2[i] = 0ull;
    float a24 = 0.f;
    for (int c = 0; c < 64; c++){
      float qc = QNq[c*28 + lane];
      u64 qc2 = pack2(qc, qc);
      const float* srow = SNw + c*28;
      const ulonglong2* s2 = (const ulonglong2*)srow;
      ulonglong2 v0=s2[0], v1=s2[1], v2=s2[2], v3=s2[3], v4=s2[4], v5=s2[5];
      a2[0] = fma2(v0.x,qc2,a2[0]); a2[1] = fma2(v0.y,qc2,a2[1]);
      a2[2] = fma2(v1.x,qc2,a2[2]); a2[3] = fma2(v1.y,qc2,a2[3]);
      a2[4] = fma2(v2.x,qc2,a2[4]); a2[5] = fma2(v2.y,qc2,a2[5]);
      a2[6] = fma2(v3.x,qc2,a2[6]); a2[7] = fma2(v3.y,qc2,a2[7]);
      a2[8] = fma2(v4.x,qc2,a2[8]); a2[9] = fma2(v4.y,qc2,a2[9]);
      a2[10]= fma2(v5.x,qc2,a2[10]);a2[11]= fma2(v5.y,qc2,a2[11]);
      a24 += srow[24]*qc;
    }
    float rq = RQq[lane];
    float acc[25];
#pragma unroll
    for (int i = 0; i < 12; i++) unpack2(a2[i], acc[2*i], acc[2*i+1]);
    acc[24] = a24;
#pragma unroll
    for (int i = 0; i < 25; i++)
      CORR[i*29 + lane] = acc[i] * sm[OFF_RS + w*25 + i] * rq;
    __syncwarp(M25);

    // ---- x1 ----
    float x[26];
#pragma unroll
    for (int e = 0; e < 25; e++) x[e] = CORR[e*29 + lane];
    x[25] = TPq[lane];
#pragma unroll
    for (int e = 0; e < 26; e++) x[e] += sm[OFF_POS + lane*27 + e];

    xblock(x, lane, sm, SCR);

    // dec1 -> SCR
    {
      u64 x2[13];
#pragma unroll
      for (int e = 0; e < 13; e++) x2[e] = pack2(x[2*e], x[2*e+1]);
#pragma unroll 2
      for (int o = 0; o < 25; o++)
        SCR[lane*28 + o] = sm[OFF_BDEC+o] + dot26p(sm + OFF_WDEC + o*28, x2);
    }
    __syncwarp(M25);

    // ---- x2 ----
#pragma unroll
    for (int e = 0; e < 25; e++) x[e] = SCR[e*28 + lane] + CORR[lane*29 + e];
    x[25] = sm[OFF_SP + w*25 + lane];
#pragma unroll
    for (int e = 0; e < 26; e++) x[e] += sm[OFF_POS + lane*27 + e];
    __syncwarp(M25);

    xblock(x, lane, sm, SCR);

    // dec2 + refined row
    float y[25];
    {
      u64 x2[13];
#pragma unroll
      for (int e = 0; e < 13; e++) x2[e] = pack2(x[2*e], x[2*e+1]);
#pragma unroll 2
      for (int o = 0; o < 25; o++)
        y[o] = sm[OFF_BDEC+o] + dot26p(sm + OFF_WDEC + o*28, x2) + CORR[lane*29 + o];
    }
#pragma unroll
    for (int o = 0; o < 25; o++) CORR[lane*29 + o] = y[o];
    __syncwarp(M25);

    // ---- attn_q: row-wise gnorm(ddof=1)/5 + softmax (|z|<=0.96 so no max-sub) ----
    {
      float s = 0.f;
#pragma unroll
      for (int j = 0; j < 25; j++) s += y[j];
      float m = s*(1.f/25.f);
      float vv = 0.f;
#pragma unroll
      for (int j = 0; j < 25; j++){ float d = y[j]-m; vv += d*d; }
      float inv = 0.2f * rsqrtf(vv*(1.f/24.f) + 1e-5f);
      float se = 0.f;
#pragma unroll
      for (int j = 0; j < 25; j++){ float e2 = __expf((y[j]-m)*inv); y[j] = e2; se += e2; }
      float is = __fdividef(1.f, se);
#pragma unroll
      for (int j = 0; j < 25; j++) SCR[lane*28 + j] = y[j]*is;
    }
    __syncwarp(M25);
    {
      float s = 0.f;
#pragma unroll
      for (int i = 0; i < 25; i++) s += SCR[i*28 + lane];
      ATTQw[lane] = s;
    }
    __syncwarp(M25);

    // ---- attn_s: column-wise gnorm + softmax ----
    {
      float col[25];
#pragma unroll
      for (int i = 0; i < 25; i++) col[i] = CORR[i*29 + lane];
      float s = 0.f;
#pragma unroll
      for (int i = 0; i < 25; i++) s += col[i];
      float m = s*(1.f/25.f);
      float vv = 0.f;
#pragma unroll
      for (int i = 0; i < 25; i++){ float d = col[i]-m; vv += d*d; }
      float inv = 0.2f * rsqrtf(vv*(1.f/24.f) + 1e-5f);
      float se = 0.f;
#pragma unroll
      for (int i = 0; i < 25; i++){ float e2 = __expf((col[i]-m)*inv); col[i] = e2; se += e2; }
      float is = __fdividef(1.f, se);
#pragma unroll
      for (int i = 0; i < 25; i++) SCR[i*28 + lane] = col[i]*is;
    }
    __syncwarp(M25);
    {
      float s = 0.f;
#pragma unroll
      for (int j = 0; j < 25; j++) s += SCR[lane*28 + j];
      ATTSw[lane] = s;
    }
  }
  __syncwarp();

  // ---- pooling + cosine sim ----
  {
    int c0 = lane, c1 = lane + 32;
    float sp0=0.f, sp1=0.f, qp0=0.f, qp1=0.f;
#pragma unroll
    for (int t = 0; t < 25; t++){
      float as_ = ATTSw[t], aq_ = ATTQw[t];
      sp0 += as_ * SNw[c0*28 + t];
      sp1 += as_ * SNw[c1*28 + t];
      qp0 += aq_ * QNq[c0*28 + t];
      qp1 += aq_ * QNq[c1*28 + t];
    }
    sp0 *= 0.04f; sp1 *= 0.04f; qp0 *= 0.04f; qp1 *= 0.04f;
    float dd = sp0*qp0 + sp1*qp1;
    float na = sp0*sp0 + sp1*sp1;
    float nb = qp0*qp0 + qp1*qp1;
#pragma unroll
    for (int off = 16; off; off >>= 1){
      dd += __shfl_xor_sync(0xFFFFFFFFu, dd, off);
      na += __shfl_xor_sync(0xFFFFFFFFu, na, off);
      nb += __shfl_xor_sync(0xFFFFFFFFu, nb, off);
    }
    if (lane == 0){
      float n1 = fmaxf(sqrtf(na), 1e-8f);
      float n2 = fmaxf(sqrtf(nb), 1e-8f);
      out[q*WAYv + w] = dd / (n1*n2) * 5.0f;
    }
  }
}

// ---------------- launch ----------------
extern "C" void kernel_launch(void* const* d_in, const int* in_sizes, int n_in,
                              void* d_out, int out_size)
{
  const float* spt    = (const float*)d_in[0];
  const float* qry    = (const float*)d_in[1];
  const float* proj_w = (const float*)d_in[2];
  const float* proj_b = (const float*)d_in[3];
  const float* pos_x  = (const float*)d_in[4];
  const float* pos_y  = (const float*)d_in[5];
  const float* ln1_g  = (const float*)d_in[6];
  const float* ln1_b  = (const float*)d_in[7];
  const float* qkv_w  = (const float*)d_in[8];
  const float* qkv_b  = (const float*)d_in[9];
  const float* attn_w = (const float*)d_in[10];
  const float* attn_b = (const float*)d_in[11];
  const float* ln2_g  = (const float*)d_in[12];
  const float* ln2_b  = (const float*)d_in[13];
  const float* fc1_w  = (const float*)d_in[14];
  const float* fc1_b  = (const float*)d_in[15];
  const float* fc2_w  = (const float*)d_in[16];
  const float* fc2_b  = (const float*)d_in[17];
  const float* dec_w  = (const float*)d_in[18];
  const float* dec_b  = (const float*)d_in[19];
  float* out = (float*)d_out;

  float *qn, *rq, *tp, *sn, *rs, *sp;
  cudaGetSymbolAddress((void**)&qn, g_qn);
  cudaGetSymbolAddress((void**)&rq, g_rq);
  cudaGetSymbolAddress((void**)&tp, g_tp);
  cudaGetSymbolAddress((void**)&sn, g_sn);
  cudaGetSymbolAddress((void**)&rs, g_rs);
  cudaGetSymbolAddress((void**)&sp, g_sp);

  prep_kernel<<<WAYv, 32>>>(spt, proj_w, proj_b, sn, rs, sp);
  prep_kernel<<<NQv, 32>>>(qry, proj_w, proj_b, qn, rq, tp);

  size_t shmem = SMEM_FLOATS * sizeof(float);
  static int configured = -1;
  if (configured < 0){
    cudaFuncSetAttribute(pair_kernel, cudaFuncAttributeMaxDynamicSharedMemorySize, (int)shmem);
    configured = 1;
  }
  pair_kernel<<<NQv/QPB, BLK, shmem>>>(
      pos_x, pos_y, ln1_g, ln1_b, qkv_w, qkv_b, attn_w, attn_b,
      ln2_g, ln2_b, fc1_w, fc1_b, fc2_w, fc2_b, dec_w, dec_b, out);
}